// round 14
// baseline (speedup 1.0000x reference)
#include <cuda_runtime.h>
#include <cuda_fp16.h>
#include <cstdint>

// ---------------------------------------------------------------------------
// B=8, L=4096, D=1024, H=8, DH=128, WIN=128; M = 32768.
// GEMMs: mma.sync m16n8k16 fp16 fp32-acc (pipe-saturated). Two variants:
//  - gemm_fp16   : CTA 128x256, 1 CTA/SM, 3-stage (qkv, ff1 — many waves)
//  - gemm_fp16_sm: CTA 128x128, 2 CTA/SM, 2-stage (out, ff2 — tail cut)
// Attention: persistent 296 CTAs (launch #4). Prep fused into 2 launches.
// ---------------------------------------------------------------------------

__device__ float  g_ada [8 * 6144];
__device__ __half g_x1  [33554432];
__device__ __half g_qkv [100663296];
__device__ __half g_o   [33554432];
__device__ float  g_res [33554432];
__device__ __half g_h   [33554432];
__device__ __half g_h1  [134217728];
__device__ float2 g_rope[8192];
__device__ __half g_wqkv[3145728];
__device__ __half g_wout[1048576];
__device__ __half g_wff1[4194304];
__device__ __half g_wff2[4194304];

// ---------------------------------------------------------------------------
// helpers
// ---------------------------------------------------------------------------
__device__ __forceinline__ float gelu_tanh(float x) {
    float u = 0.7978845608028654f * (x + 0.044715f * x * x * x);
    return 0.5f * x * (1.f + tanhf(u));
}

__device__ __forceinline__ uint32_t smem_u32(const void* p) {
    uint32_t a;
    asm("{ .reg .u64 t; cvta.to.shared.u64 t, %1; cvt.u32.u64 %0, t; }" : "=r"(a) : "l"(p));
    return a;
}

__device__ __forceinline__ uint32_t h2u(half2 h) {
    uint32_t u;
    memcpy(&u, &h, 4);
    return u;
}

// perm64 operand layout: applied to BOTH A and B k-dims (dot-product invariant)
__device__ __forceinline__ int perm64h(int k) {
    const int base  = k & ~63;
    const int sb    = (k >> 5) & 1;
    const int b16   = (k >> 4) & 1;
    const int j     = (k & 15) >> 1;
    const int owner = j & 3, hi = j >> 2;
    return base + (owner * 2 + sb) * 8 + b16 * 4 + hi * 2 + (k & 1);
}
__device__ __forceinline__ int perm64c(int col) { return perm64h(col); }

__device__ __forceinline__ void mma16(float* d, uint32_t a0, uint32_t a1,
                                      uint32_t a2, uint32_t a3,
                                      uint32_t b0, uint32_t b1) {
    asm volatile(
        "mma.sync.aligned.m16n8k16.row.col.f32.f16.f16.f32 "
        "{%0,%1,%2,%3}, {%4,%5,%6,%7}, {%8,%9}, {%0,%1,%2,%3};"
        : "+f"(d[0]), "+f"(d[1]), "+f"(d[2]), "+f"(d[3])
        : "r"(a0), "r"(a1), "r"(a2), "r"(a3), "r"(b0), "r"(b1));
}

__device__ __forceinline__ void ldsm_x4(uint32_t& r0, uint32_t& r1,
                                        uint32_t& r2, uint32_t& r3, uint32_t a) {
    asm volatile("ldmatrix.sync.aligned.m8n8.x4.shared.b16 {%0,%1,%2,%3}, [%4];"
                 : "=r"(r0), "=r"(r1), "=r"(r2), "=r"(r3) : "r"(a));
}
__device__ __forceinline__ void ldsm_x4t(uint32_t& r0, uint32_t& r1,
                                         uint32_t& r2, uint32_t& r3, uint32_t a) {
    asm volatile("ldmatrix.sync.aligned.m8n8.x4.trans.shared.b16 {%0,%1,%2,%3}, [%4];"
                 : "=r"(r0), "=r"(r1), "=r"(r2), "=r"(r3) : "r"(a));
}

__device__ __forceinline__ uint4 lds128(uint32_t a) {
    uint4 v;
    asm volatile("ld.shared.v4.u32 {%0,%1,%2,%3}, [%4];"
                 : "=r"(v.x), "=r"(v.y), "=r"(v.z), "=r"(v.w) : "r"(a));
    return v;
}

__device__ __forceinline__ void cp16(uint32_t dst, const void* src) {
    asm volatile("cp.async.cg.shared.global [%0], [%1], 16;" :: "r"(dst), "l"(src));
}
#define CP_COMMIT() asm volatile("cp.async.commit_group;" ::: "memory")
#define CP_WAIT1()  asm volatile("cp.async.wait_group 1;"  ::: "memory")
#define CP_WAIT0()  asm volatile("cp.async.wait_group 0;"  ::: "memory")

// ---------------------------------------------------------------------------
// device transpose helper: Wt[n][perm64(k)] = fp16(W[k][n]), 32x32 tile
// ---------------------------------------------------------------------------
__device__ __forceinline__ void dev_transpose(
    const float* __restrict__ W, __half* __restrict__ Wt,
    int K, int N, int kb, int nb, float* sh)
{
    const int tx = threadIdx.x & 31, ty = threadIdx.x >> 5;   // 32 x 8
    #pragma unroll
    for (int i = 0; i < 4; i++)
        sh[(ty + 8 * i) * 33 + tx] = W[(size_t)(kb + ty + 8 * i) * N + nb + tx];
    __syncthreads();
    #pragma unroll
    for (int i = 0; i < 4; i++)
        Wt[(size_t)(nb + ty + 8 * i) * K + perm64h(kb + tx)] =
            __float2half_rn(sh[tx * 33 + ty + 8 * i]);
}

// ---------------------------------------------------------------------------
// Kernel 1: prep = ada (0..23) + rope (24..55) + W_qkv transpose (56..3127)
// ---------------------------------------------------------------------------
__global__ void __launch_bounds__(256) prep_kernel(
    const float* __restrict__ ctx, const float* __restrict__ W_ada,
    const float* __restrict__ b_ada, float* __restrict__ ada,
    float2* __restrict__ rope,
    const float* __restrict__ W_qkv, __half* __restrict__ wqkv)
{
    __shared__ float sh[8448];
    const int b = blockIdx.x;
    if (b < 24) {
        for (int i = threadIdx.x; i < 8192; i += 256) {
            float c = ctx[i];
            sh[i] = c / (1.f + __expf(-c));
        }
        __syncthreads();
        const int col = b * 256 + threadIdx.x;
        float acc[8] = {0, 0, 0, 0, 0, 0, 0, 0};
        for (int k = 0; k < 1024; k++) {
            float w = W_ada[(size_t)k * 6144 + col];
            #pragma unroll
            for (int bb = 0; bb < 8; bb++) acc[bb] += sh[bb * 1024 + k] * w;
        }
        float bv = b_ada[col];
        #pragma unroll
        for (int bb = 0; bb < 8; bb++) ada[bb * 6144 + col] = acc[bb] + bv;
    } else if (b < 56) {
        int idx = (b - 24) * 256 + threadIdx.x;
        if (idx < 8192) {
            int pos = idx >> 6;
            int i   = idx & 63;
            float freq = powf(10000.f, -(float)(2 * i) / 128.f);
            float ang  = (float)pos * freq;
            rope[idx] = make_float2(sinf(ang), cosf(ang));
        }
    } else {
        const int t = b - 56;
        const int nb = (t % 96) * 32;
        const int kb = (t / 96) * 32;
        dev_transpose(W_qkv, wqkv, 1024, 3072, kb, nb, sh);
    }
}

// ---------------------------------------------------------------------------
// Kernel 2: rmsnorm + modulate -> fp16 perm64 (+ weight transposes, norm1)
// ---------------------------------------------------------------------------
__global__ void __launch_bounds__(256) norm_mod(
    const float* __restrict__ x, const float* __restrict__ scale,
    const float* __restrict__ ada, int shOff, int scOff,
    __half* __restrict__ y,
    const float* __restrict__ W_out, __half* __restrict__ wout,
    const float* __restrict__ W_ff1, __half* __restrict__ wff1,
    const float* __restrict__ W_ff2, __half* __restrict__ wff2)
{
    __shared__ float sh[1056];
    const int row = blockIdx.x;
    if (row >= 32768) {
        int t = row - 32768;
        if (t < 1024) {
            dev_transpose(W_out, wout, 1024, 1024, (t / 32) * 32, (t % 32) * 32, sh);
        } else if (t < 5120) {
            t -= 1024;
            dev_transpose(W_ff1, wff1, 1024, 4096, (t / 128) * 32, (t % 128) * 32, sh);
        } else {
            t -= 5120;
            dev_transpose(W_ff2, wff2, 4096, 1024, (t / 32) * 32, (t % 32) * 32, sh);
        }
        return;
    }
    const int b = row >> 12;
    const float4 v = ((const float4*)(x + (size_t)row * 1024))[threadIdx.x];

    float ss = v.x * v.x + v.y * v.y + v.z * v.z + v.w * v.w;
    #pragma unroll
    for (int o = 16; o > 0; o >>= 1) ss += __shfl_xor_sync(0xffffffffu, ss, o);
    if ((threadIdx.x & 31) == 0) sh[threadIdx.x >> 5] = ss;
    __syncthreads();
    float tot = 0.f;
    #pragma unroll
    for (int i = 0; i < 8; i++) tot += sh[i];
    const float r = rsqrtf(tot * (1.f / 1024.f) + 1e-5f);

    const int c = threadIdx.x * 4;
    const float* ab = ada + b * 6144;
    const float4 s   = *(const float4*)(scale + c);
    const float4 shv = *(const float4*)(ab + shOff + c);
    const float4 scm = *(const float4*)(ab + scOff + c);
    float o0 = v.x * r * s.x * (1.f + scm.x) + shv.x;
    float o1 = v.y * r * s.y * (1.f + scm.y) + shv.y;
    float o2 = v.z * r * s.z * (1.f + scm.z) + shv.z;
    float o3 = v.w * r * s.w * (1.f + scm.w) + shv.w;
    __half* yr = y + (size_t)row * 1024;
    *(half2*)(yr + perm64c(c))     = __floats2half2_rn(o0, o1);
    *(half2*)(yr + perm64c(c + 2)) = __floats2half2_rn(o2, o3);
}

// ---------------------------------------------------------------------------
// Kernel 4a: fp16 GEMM, CTA 128x256 (qkv MODE 3, ff1 MODE 1)
// ---------------------------------------------------------------------------
#define STAGE_BYTES 49152
#define GEMM_SMEM  (3 * STAGE_BYTES)

template <int MODE>
__global__ void __launch_bounds__(256, 1) gemm_fp16(
    const __half* __restrict__ A, const __half* __restrict__ Bt,
    const float* __restrict__ bias,
    float* __restrict__ C, __half* __restrict__ Ch,
    int N, int K,
    const float* __restrict__ res, const float* __restrict__ gate)
{
    extern __shared__ char smem[];
    const uint32_t sm_u = smem_u32(smem);

    const int tid  = threadIdx.x;
    const int lane = tid & 31;
    const int warp = tid >> 5;
    const int g    = lane >> 2, tig = lane & 3;
    const int wm   = warp & 1;
    const int wn   = warp >> 1;
    const int cm   = blockIdx.y << 7;
    const int cn   = blockIdx.x << 8;
    const int KT   = K >> 6;

    const int f_row = tid >> 3;
    const int f_ch  = tid & 7;

    auto fill = [&](int kt, int s) {
        const uint32_t sb_ = sm_u + s * STAGE_BYTES;
        const __half* Ag = A + (size_t)(cm + f_row) * K + (kt << 6) + f_ch * 8;
        #pragma unroll
        for (int i = 0; i < 4; i++) {
            const int row = f_row + i * 32;
            cp16(sb_ + row * 128 + ((f_ch ^ (row & 7)) << 4),
                 Ag + (size_t)i * 32 * K);
        }
        const __half* Bg = Bt + (size_t)(cn + f_row) * K + (kt << 6) + f_ch * 8;
        #pragma unroll
        for (int i = 0; i < 8; i++) {
            const int row = f_row + i * 32;
            cp16(sb_ + 16384 + row * 128 + ((f_ch ^ (row & 7)) << 4),
                 Bg + (size_t)i * 32 * K);
        }
    };

    float acc[4][8][4];
    #pragma unroll
    for (int mt = 0; mt < 4; mt++)
        #pragma unroll
        for (int nt = 0; nt < 8; nt++)
            #pragma unroll
            for (int i = 0; i < 4; i++) acc[mt][nt][i] = 0.f;

    fill(0, 0); CP_COMMIT();
    if (KT > 1) fill(1, 1);
    CP_COMMIT();

    int s = 0;
    for (int kt = 0; kt < KT; kt++) {
        CP_WAIT1();
        __syncthreads();

        const uint32_t a_base = sm_u + s * STAGE_BYTES;
        const uint32_t b_base = a_base + 16384;
        #pragma unroll
        for (int sb = 0; sb < 2; sb++) {
            const int chn = (tig << 1) | sb;
            uint4 al[4], ah[4];
            #pragma unroll
            for (int mt = 0; mt < 4; mt++) {
                const int rl = wm * 64 + mt * 16 + g;
                al[mt] = lds128(a_base + rl * 128 + ((chn ^ (rl & 7)) << 4));
                ah[mt] = lds128(a_base + (rl + 8) * 128 + ((chn ^ (rl & 7)) << 4));
            }
            #pragma unroll
            for (int nt = 0; nt < 8; nt++) {
                const int rb = wn * 64 + nt * 8 + g;
                const uint4 bb = lds128(b_base + rb * 128 + ((chn ^ (rb & 7)) << 4));
                #pragma unroll
                for (int mt = 0; mt < 4; mt++) {
                    mma16(acc[mt][nt], al[mt].x, ah[mt].x, al[mt].y, ah[mt].y,
                          bb.x, bb.y);
                    mma16(acc[mt][nt], al[mt].z, ah[mt].z, al[mt].w, ah[mt].w,
                          bb.z, bb.w);
                }
            }
        }
        if (kt + 2 < KT) fill(kt + 2, (s + 2 >= 3) ? s - 1 : s + 2);
        CP_COMMIT();
        s = (s + 1 == 3) ? 0 : s + 1;
    }

    #pragma unroll
    for (int mt = 0; mt < 4; mt++) {
        const int row0 = cm + wm * 64 + mt * 16 + g;
        #pragma unroll
        for (int nt = 0; nt < 8; nt++) {
            const int col = cn + wn * 64 + nt * 8 + (tig << 1);
            const float bi0 = bias[col], bi1 = bias[col + 1];
            float v0 = acc[mt][nt][0] + bi0;
            float v1 = acc[mt][nt][1] + bi1;
            float v2 = acc[mt][nt][2] + bi0;
            float v3 = acc[mt][nt][3] + bi1;
            if (MODE == 1) {
                v0 = gelu_tanh(v0); v1 = gelu_tanh(v1);
                v2 = gelu_tanh(v2); v3 = gelu_tanh(v3);
                const int p = perm64c(col);
                *(half2*)(Ch + (size_t)row0 * N + p)       = __floats2half2_rn(v0, v1);
                *(half2*)(Ch + (size_t)(row0 + 8) * N + p) = __floats2half2_rn(v2, v3);
            } else {   // MODE 3
                *(half2*)(Ch + (size_t)row0 * N + col)       = __floats2half2_rn(v0, v1);
                *(half2*)(Ch + (size_t)(row0 + 8) * N + col) = __floats2half2_rn(v2, v3);
            }
        }
    }
}

// ---------------------------------------------------------------------------
// Kernel 4b: fp16 GEMM, CTA 128x128, 2 CTAs/SM (out & ff2: MODE 2 epilogue)
//   Smaller CTAs cut wave-quantization tails on N=1024 GEMMs.
// ---------------------------------------------------------------------------
#define STAGE_SM 32768
#define GEMM_SMEM_SM (2 * STAGE_SM)

__global__ void __launch_bounds__(256, 2) gemm_fp16_sm(
    const __half* __restrict__ A, const __half* __restrict__ Bt,
    const float* __restrict__ bias, float* __restrict__ C,
    int N, int K,
    const float* __restrict__ res, const float* __restrict__ gate)
{
    extern __shared__ char smem[];
    const uint32_t sm_u = smem_u32(smem);

    const int tid  = threadIdx.x;
    const int lane = tid & 31;
    const int warp = tid >> 5;
    const int g    = lane >> 2, tig = lane & 3;
    const int wm   = warp & 3;     // 0..3 -> 32-row group
    const int wn   = warp >> 2;    // 0..1 -> 64-col group
    const int cm   = blockIdx.y << 7;
    const int cn   = blockIdx.x << 7;
    const int KT   = K >> 6;

    const int f_row = tid >> 3;
    const int f_ch  = tid & 7;

    auto fill = [&](int kt, int s) {
        const uint32_t sb_ = sm_u + s * STAGE_SM;
        const __half* Ag = A + (size_t)(cm + f_row) * K + (kt << 6) + f_ch * 8;
        #pragma unroll
        for (int i = 0; i < 4; i++) {
            const int row = f_row + i * 32;
            cp16(sb_ + row * 128 + ((f_ch ^ (row & 7)) << 4),
                 Ag + (size_t)i * 32 * K);
        }
        const __half* Bg = Bt + (size_t)(cn + f_row) * K + (kt << 6) + f_ch * 8;
        #pragma unroll
        for (int i = 0; i < 4; i++) {
            const int row = f_row + i * 32;
            cp16(sb_ + 16384 + row * 128 + ((f_ch ^ (row & 7)) << 4),
                 Bg + (size_t)i * 32 * K);
        }
    };

    float acc[2][8][4];
    #pragma unroll
    for (int mt = 0; mt < 2; mt++)
        #pragma unroll
        for (int nt = 0; nt < 8; nt++)
            #pragma unroll
            for (int i = 0; i < 4; i++) acc[mt][nt][i] = 0.f;

    fill(0, 0); CP_COMMIT();

    for (int kt = 0; kt < KT; kt++) {
        const int buf = kt & 1;
        if (kt + 1 < KT) { fill(kt + 1, buf ^ 1); CP_COMMIT(); CP_WAIT1(); }
        else             { CP_WAIT0(); }
        __syncthreads();

        const uint32_t a_base = sm_u + buf * STAGE_SM;
        const uint32_t b_base = a_base + 16384;
        #pragma unroll
        for (int sb = 0; sb < 2; sb++) {
            const int chn = (tig << 1) | sb;
            uint4 al[2], ah[2];
            #pragma unroll
            for (int mt = 0; mt < 2; mt++) {
                const int rl = wm * 32 + mt * 16 + g;
                al[mt] = lds128(a_base + rl * 128 + ((chn ^ (rl & 7)) << 4));
                ah[mt] = lds128(a_base + (rl + 8) * 128 + ((chn ^ (rl & 7)) << 4));
            }
            #pragma unroll
            for (int nt = 0; nt < 8; nt++) {
                const int rb = wn * 64 + nt * 8 + g;
                const uint4 bb = lds128(b_base + rb * 128 + ((chn ^ (rb & 7)) << 4));
                #pragma unroll
                for (int mt = 0; mt < 2; mt++) {
                    mma16(acc[mt][nt], al[mt].x, ah[mt].x, al[mt].y, ah[mt].y,
                          bb.x, bb.y);
                    mma16(acc[mt][nt], al[mt].z, ah[mt].z, al[mt].w, ah[mt].w,
                          bb.z, bb.w);
                }
            }
        }
        __syncthreads();
    }

    const int bb_i = cm >> 12;
    #pragma unroll
    for (int mt = 0; mt < 2; mt++) {
        const int row0 = cm + wm * 32 + mt * 16 + g;
        #pragma unroll
        for (int nt = 0; nt < 8; nt++) {
            const int col = cn + wn * 64 + nt * 8 + (tig << 1);
            const float bi0 = bias[col], bi1 = bias[col + 1];
            const float g0 = gate[bb_i * 6144 + col];
            const float g1 = gate[bb_i * 6144 + col + 1];
            const float2 r0 = *(const float2*)(res + (size_t)row0 * N + col);
            const float2 r1 = *(const float2*)(res + (size_t)(row0 + 8) * N + col);
            float v0 = r0.x + g0 * (acc[mt][nt][0] + bi0);
            float v1 = r0.y + g1 * (acc[mt][nt][1] + bi1);
            float v2 = r1.x + g0 * (acc[mt][nt][2] + bi0);
            float v3 = r1.y + g1 * (acc[mt][nt][3] + bi1);
            *(float2*)(C + (size_t)row0 * N + col)       = make_float2(v0, v1);
            *(float2*)(C + (size_t)(row0 + 8) * N + col) = make_float2(v2, v3);
        }
    }
}

// ---------------------------------------------------------------------------
// Kernel 5: persistent windowed attention (R13, launch #4)
// ---------------------------------------------------------------------------
#define AT_BUF  98304
#define ATTN_SMEM_BYTES AT_BUF
#define AT_NTILES 2048
#define AT_GRID   296

__global__ void __launch_bounds__(256, 2) attn_kernel(
    const __half* __restrict__ qkv, __half* __restrict__ obuf,
    const float2* __restrict__ rope)
{
    extern __shared__ char sha[];
    const uint32_t sm_u = smem_u32(sha);

    const int tid  = threadIdx.x;
    const int lane = tid & 31, warp = tid >> 5;
    const int tig  = lane & 3;

    const int s_row = tid >> 4, s_ch = tid & 15;

    auto stage = [&](int tile) {
        const int w = tile >> 3, h = tile & 7;
        const size_t rb = (size_t)w * 128;
        const __half* base = qkv + (rb + s_row) * 3072 + h * 128 + s_ch * 8;
        #pragma unroll
        for (int i = 0; i < 8; i++) {
            const int r = s_row + i * 16;
            const uint32_t off = r * 256 + ((s_ch ^ (r & 7)) << 4);
            const __half* src = base + (size_t)i * 16 * 3072;
            cp16(sm_u + off,         src);
            cp16(sm_u + 32768 + off, src + 1024);
            cp16(sm_u + 65536 + off, src + 2048);
        }
    };

    const int m0 = warp * 16;
    const int l7 = lane & 7;
    const int a_row = m0 + l7 + ((lane & 8) ? 8 : 0);
    const int a_kc8 = (lane & 16) ? 1 : 0;
    const int b_row = l7 + ((lane & 16) ? 8 : 0);
    const int b_kc8 = (lane & 8) ? 1 : 0;
    const int v_row = l7 + ((lane & 8) ? 8 : 0);
    const int v_dc8 = (lane & 16) ? 1 : 0;

    const uint32_t q_u = sm_u;
    const uint32_t k_u = sm_u + 32768;
    const uint32_t v_u = sm_u + 65536;

    stage(blockIdx.x); CP_COMMIT();

    for (int tile = blockIdx.x; tile < AT_NTILES; tile += AT_GRID) {
        CP_WAIT0();
        __syncthreads();

        const int h = tile & 7;
        const size_t rowbase = (size_t)(tile >> 3) * 128;

        #pragma unroll
        for (int it = 0; it < 16; it++) {
            const int task = tid + it * 256;
            const int i  = task >> 5;
            const int dp = task & 31;
            const int d  = dp << 1;
            const int clo = (d >> 3) ^ (i & 7);
            const int chi = ((d + 64) >> 3) ^ (i & 7);
            const int ib  = (d << 1) & 15;
            const uint32_t lo = i * 256 + (clo << 4) + ib;
            const uint32_t hi = i * 256 + (chi << 4) + ib;
            const float2 sc_lo = rope[i * 64 + dp];
            const float2 sc_hi = rope[i * 64 + dp + 32];
            {
                half2* plo = (half2*)(sha + lo);
                half2* phi = (half2*)(sha + hi);
                float2 a = __half22float2(*plo);
                float2 b = __half22float2(*phi);
                *plo = __floats2half2_rn(a.x * sc_lo.y - b.x * sc_lo.x,
                                         a.y * sc_lo.y - b.y * sc_lo.x);
                *phi = __floats2half2_rn(b.x * sc_hi.y + a.x * sc_hi.x,
                                         b.y * sc_hi.y + a.y * sc_hi.x);
            }
            {
                half2* plo = (half2*)(sha + 32768 + lo);
                half2* phi = (half2*)(sha + 32768 + hi);
                float2 a = __half22float2(*plo);
                float2 b = __half22float2(*phi);
                *plo = __floats2half2_rn(a.x * sc_lo.y - b.x * sc_lo.x,
                                         a.y * sc_lo.y - b.y * sc_lo.x);
                *phi = __floats2half2_rn(b.x * sc_hi.y + a.x * sc_hi.x,
                                         b.y * sc_hi.y + a.y * sc_hi.x);
            }
        }
        __syncthreads();

        float acc[16][4];
        #pragma unroll
        for (int nt = 0; nt < 16; nt++)
            #pragma unroll
            for (int i = 0; i < 4; i++) acc[nt][i] = 0.f;

        #pragma unroll
        for (int kc = 0; kc < 8; kc++) {
            uint32_t a0, a1, a2, a3;
            const int ca = (kc * 2 + a_kc8) ^ (a_row & 7);
            ldsm_x4(a0, a1, a2, a3, q_u + a_row * 256 + (ca << 4));
            #pragma unroll
            for (int np = 0; np < 8; np++) {
                const int row = np * 16 + b_row;
                const int cb = (kc * 2 + b_kc8) ^ (row & 7);
                uint32_t b0, b1, c0, c1;
                ldsm_x4(b0, b1, c0, c1, k_u + row * 256 + (cb << 4));
                mma16(acc[2 * np],     a0, a1, a2, a3, b0, b1);
                mma16(acc[2 * np + 1], a0, a1, a2, a3, c0, c1);
            }
        }

        const float scl = 0.08838834764831845f;
        float mx0 = -1e30f, mx1 = -1e30f;
        #pragma unroll
        for (int nt = 0; nt < 16; nt++) {
            acc[nt][0] *= scl; acc[nt][1] *= scl;
            acc[nt][2] *= scl; acc[nt][3] *= scl;
            mx0 = fmaxf(mx0, fmaxf(acc[nt][0], acc[nt][1]));
            mx1 = fmaxf(mx1, fmaxf(acc[nt][2], acc[nt][3]));
        }
        mx0 = fmaxf(mx0, __shfl_xor_sync(0xffffffffu, mx0, 1));
        mx0 = fmaxf(mx0, __shfl_xor_sync(0xffffffffu, mx0, 2));
        mx1 = fmaxf(mx1, __shfl_xor_sync(0xffffffffu, mx1, 1));
        mx1 = fmaxf(mx1, __shfl_xor_sync(0xffffffffu, mx1, 2));

        float s0 = 0.f, s1 = 0.f;
        #pragma unroll
        for (int nt = 0; nt < 16; nt++) {
            acc[nt][0] = __expf(acc[nt][0] - mx0);
            acc[nt][1] = __expf(acc[nt][1] - mx0);
            acc[nt][2] = __expf(acc[nt][2] - mx1);
            acc[nt][3] = __expf(acc[nt][3] - mx1);
            s0 += acc[nt][0] + acc[nt][1];
            s1 += acc[nt][2] + acc[nt][3];
        }
        s0 += __shfl_xor_sync(0xffffffffu, s0, 1);
        s0 += __shfl_xor_sync(0xffffffffu, s0, 2);
        s1 += __shfl_xor_sync(0xffffffffu, s1, 1);
        s1 += __shfl_xor_sync(0xffffffffu, s1, 2);
        const float i0 = 1.f / s0, i1 = 1.f / s1;

        uint32_t p[32];
        #pragma unroll
        for (int kc = 0; kc < 8; kc++) {
            p[4 * kc + 0] = h2u(__floats2half2_rn(acc[2 * kc][0] * i0, acc[2 * kc][1] * i0));
            p[4 * kc + 1] = h2u(__floats2half2_rn(acc[2 * kc][2] * i1, acc[2 * kc][3] * i1));
            p[4 * kc + 2] = h2u(__floats2half2_rn(acc[2 * kc + 1][0] * i0, acc[2 * kc + 1][1] * i0));
            p[4 * kc + 3] = h2u(__floats2half2_rn(acc[2 * kc + 1][2] * i1, acc[2 * kc + 1][3] * i1));
        }

        float o[16][4];
        #pragma unroll
        for (int nt = 0; nt < 16; nt++)
            #pragma unroll
            for (int i = 0; i < 4; i++) o[nt][i] = 0.f;

        #pragma unroll
        for (int kc = 0; kc < 8; kc++) {
            #pragma unroll
            for (int dp = 0; dp < 8; dp++) {
                const int row = kc * 16 + v_row;
                const int cv = (dp * 2 + v_dc8) ^ (row & 7);
                uint32_t b0, b1, c0, c1;
                ldsm_x4t(b0, b1, c0, c1, v_u + row * 256 + (cv << 4));
                mma16(o[2 * dp],     p[4 * kc], p[4 * kc + 1], p[4 * kc + 2], p[4 * kc + 3], b0, b1);
                mma16(o[2 * dp + 1], p[4 * kc], p[4 * kc + 1], p[4 * kc + 2], p[4 * kc + 3], c0, c1);
            }
        }

        __syncthreads();
        if (tile + AT_GRID < AT_NTILES) stage(tile + AT_GRID);
        CP_COMMIT();

        const int gq = lane >> 2;
        #pragma unroll
        for (int nt = 0; nt < 16; nt++) {
            const int col = h * 128 + nt * 8 + (tig << 1);
            const int pc = perm64c(col);
            *(half2*)(obuf + (rowbase + m0 + gq) * 1024 + pc) =
                __floats2half2_rn(o[nt][0], o[nt][1]);
            *(half2*)(obuf + (rowbase + m0 + gq + 8) * 1024 + pc) =
                __floats2half2_rn(o[nt][2], o[nt][3]);
        }
    }
}

// ---------------------------------------------------------------------------
// host launcher — 8 launches; attention is #4 (profiled by ncu)
// ---------------------------------------------------------------------------
extern "C" void kernel_launch(void* const* d_in, const int* in_sizes, int n_in,
                              void* d_out, int out_size)
{
    const float* group_x = (const float*)d_in[0];
    const float* context = (const float*)d_in[1];
    const float* W_ada   = (const float*)d_in[2];
    const float* b_ada   = (const float*)d_in[3];
    const float* scale1  = (const float*)d_in[4];
    const float* W_qkv   = (const float*)d_in[5];
    const float* b_qkv   = (const float*)d_in[6];
    const float* W_out   = (const float*)d_in[7];
    const float* b_out   = (const float*)d_in[8];
    const float* scale2  = (const float*)d_in[9];
    const float* W_ff1   = (const float*)d_in[10];
    const float* b_ff1   = (const float*)d_in[11];
    const float* W_ff2   = (const float*)d_in[12];
    const float* b_ff2   = (const float*)d_in[13];
    float* out = (float*)d_out;

    float *ada, *res2;
    __half *x1, *qkv, *obuf, *hbuf, *h1, *wqkv, *wout, *wff1, *wff2;
    float2* rope;
    cudaGetSymbolAddress((void**)&ada,  g_ada);
    cudaGetSymbolAddress((void**)&x1,   g_x1);
    cudaGetSymbolAddress((void**)&qkv,  g_qkv);
    cudaGetSymbolAddress((void**)&obuf, g_o);
    cudaGetSymbolAddress((void**)&res2, g_res);
    cudaGetSymbolAddress((void**)&hbuf, g_h);
    cudaGetSymbolAddress((void**)&h1,   g_h1);
    cudaGetSymbolAddress((void**)&rope, g_rope);
    cudaGetSymbolAddress((void**)&wqkv, g_wqkv);
    cudaGetSymbolAddress((void**)&wout, g_wout);
    cudaGetSymbolAddress((void**)&wff1, g_wff1);
    cudaGetSymbolAddress((void**)&wff2, g_wff2);

    cudaFuncSetAttribute(gemm_fp16<1>, cudaFuncAttributeMaxDynamicSharedMemorySize, GEMM_SMEM);
    cudaFuncSetAttribute(gemm_fp16<3>, cudaFuncAttributeMaxDynamicSharedMemorySize, GEMM_SMEM);
    cudaFuncSetAttribute(gemm_fp16_sm, cudaFuncAttributeMaxDynamicSharedMemorySize, GEMM_SMEM_SM);
    cudaFuncSetAttribute(attn_kernel,  cudaFuncAttributeMaxDynamicSharedMemorySize, ATTN_SMEM_BYTES);

    // 1: ada + rope + W_qkv transpose
    prep_kernel<<<3128, 256>>>(context, W_ada, b_ada, ada, rope, W_qkv, wqkv);

    // 2: norm1 (+ wout/wff1/wff2 transposes in extra blocks)
    norm_mod<<<32768 + 9216, 256>>>(group_x, scale1, ada, 0, 1024, x1,
                                    W_out, wout, W_ff1, wff1, W_ff2, wff2);

    // 3: qkv = x1 @ W_qkv + b_qkv -> fp16 natural   (N=3072, K=1024)
    gemm_fp16<3><<<dim3(12, 256), 256, GEMM_SMEM>>>(x1, wqkv, b_qkv, nullptr, qkv,
                                                    3072, 1024, nullptr, nullptr);

    // 4 (profiled): persistent attention
    attn_kernel<<<AT_GRID, 256, ATTN_SMEM_BYTES>>>(qkv, obuf, rope);

    // 5: res2 = group_x + g_msa * (obuf @ W_out + b_out)   (N=1024, K=1024)
    gemm_fp16_sm<<<dim3(8, 256), 256, GEMM_SMEM_SM>>>(obuf, wout, b_out, res2,
                                                      1024, 1024, group_x, ada + 2048);

    // 6: norm2
    norm_mod<<<32768, 256>>>(res2, scale2, ada, 3072, 4096, hbuf,
                             nullptr, nullptr, nullptr, nullptr, nullptr, nullptr);

    // 7: h1 = gelu(hbuf @ W_ff1 + b_ff1) -> fp16 perm64  (N=4096, K=1024)
    gemm_fp16<1><<<dim3(16, 256), 256, GEMM_SMEM>>>(hbuf, wff1, b_ff1, nullptr, h1,
                                                    4096, 1024, nullptr, nullptr);
    // 8: out = res2 + g_mlp * (h1 @ W_ff2 + b_ff2)        (N=1024, K=4096)
    gemm_fp16_sm<<<dim3(8, 256), 256, GEMM_SMEM_SM>>>(h1, wff2, b_ff2, out,
                                                      1024, 4096, res2, ada + 5120);
}

// round 15
// speedup vs baseline: 1.0227x; 1.0227x over previous
#include <cuda_runtime.h>
#include <cuda_fp16.h>
#include <cstdint>

// ---------------------------------------------------------------------------
// B=8, L=4096, D=1024, H=8, DH=128, WIN=128; M = 32768.
// GEMMs: mma.sync m16n8k16 fp16 fp32-acc (pipe-saturated), CTA 128x256,
// 3-stage cp.async (R13 config restored). GELU epilogue now uses the exact
// sigmoid identity with __expf (1 MUFU) instead of software tanhf.
// Attention: persistent 296 CTAs (launch #4). Prep fused into 2 launches.
// ---------------------------------------------------------------------------

__device__ float  g_ada [8 * 6144];
__device__ __half g_x1  [33554432];
__device__ __half g_qkv [100663296];
__device__ __half g_o   [33554432];
__device__ float  g_res [33554432];
__device__ __half g_h   [33554432];
__device__ __half g_h1  [134217728];
__device__ float2 g_rope[8192];
__device__ __half g_wqkv[3145728];
__device__ __half g_wout[1048576];
__device__ __half g_wff1[4194304];
__device__ __half g_wff2[4194304];

// ---------------------------------------------------------------------------
// helpers
// ---------------------------------------------------------------------------
__device__ __forceinline__ float gelu_fast(float x) {
    // exact identity: 0.5*x*(1+tanh(u)) == x * sigmoid(2u), u = c*(x+0.044715x^3)
    const float t = 1.5957691216057308f * (x + 0.044715f * x * x * x);
    return __fdividef(x, 1.f + __expf(-t));
}

__device__ __forceinline__ uint32_t smem_u32(const void* p) {
    uint32_t a;
    asm("{ .reg .u64 t; cvta.to.shared.u64 t, %1; cvt.u32.u64 %0, t; }" : "=r"(a) : "l"(p));
    return a;
}

__device__ __forceinline__ uint32_t h2u(half2 h) {
    uint32_t u;
    memcpy(&u, &h, 4);
    return u;
}

// perm64 operand layout: applied to BOTH A and B k-dims (dot-product invariant)
__device__ __forceinline__ int perm64h(int k) {
    const int base  = k & ~63;
    const int sb    = (k >> 5) & 1;
    const int b16   = (k >> 4) & 1;
    const int j     = (k & 15) >> 1;
    const int owner = j & 3, hi = j >> 2;
    return base + (owner * 2 + sb) * 8 + b16 * 4 + hi * 2 + (k & 1);
}
__device__ __forceinline__ int perm64c(int col) { return perm64h(col); }

__device__ __forceinline__ void mma16(float* d, uint32_t a0, uint32_t a1,
                                      uint32_t a2, uint32_t a3,
                                      uint32_t b0, uint32_t b1) {
    asm volatile(
        "mma.sync.aligned.m16n8k16.row.col.f32.f16.f16.f32 "
        "{%0,%1,%2,%3}, {%4,%5,%6,%7}, {%8,%9}, {%0,%1,%2,%3};"
        : "+f"(d[0]), "+f"(d[1]), "+f"(d[2]), "+f"(d[3])
        : "r"(a0), "r"(a1), "r"(a2), "r"(a3), "r"(b0), "r"(b1));
}

__device__ __forceinline__ void ldsm_x4(uint32_t& r0, uint32_t& r1,
                                        uint32_t& r2, uint32_t& r3, uint32_t a) {
    asm volatile("ldmatrix.sync.aligned.m8n8.x4.shared.b16 {%0,%1,%2,%3}, [%4];"
                 : "=r"(r0), "=r"(r1), "=r"(r2), "=r"(r3) : "r"(a));
}
__device__ __forceinline__ void ldsm_x4t(uint32_t& r0, uint32_t& r1,
                                         uint32_t& r2, uint32_t& r3, uint32_t a) {
    asm volatile("ldmatrix.sync.aligned.m8n8.x4.trans.shared.b16 {%0,%1,%2,%3}, [%4];"
                 : "=r"(r0), "=r"(r1), "=r"(r2), "=r"(r3) : "r"(a));
}

__device__ __forceinline__ uint4 lds128(uint32_t a) {
    uint4 v;
    asm volatile("ld.shared.v4.u32 {%0,%1,%2,%3}, [%4];"
                 : "=r"(v.x), "=r"(v.y), "=r"(v.z), "=r"(v.w) : "r"(a));
    return v;
}

__device__ __forceinline__ void cp16(uint32_t dst, const void* src) {
    asm volatile("cp.async.cg.shared.global [%0], [%1], 16;" :: "r"(dst), "l"(src));
}
#define CP_COMMIT() asm volatile("cp.async.commit_group;" ::: "memory")
#define CP_WAIT1()  asm volatile("cp.async.wait_group 1;"  ::: "memory")
#define CP_WAIT0()  asm volatile("cp.async.wait_group 0;"  ::: "memory")

// ---------------------------------------------------------------------------
// device transpose helper: Wt[n][perm64(k)] = fp16(W[k][n]), 32x32 tile
// ---------------------------------------------------------------------------
__device__ __forceinline__ void dev_transpose(
    const float* __restrict__ W, __half* __restrict__ Wt,
    int K, int N, int kb, int nb, float* sh)
{
    const int tx = threadIdx.x & 31, ty = threadIdx.x >> 5;   // 32 x 8
    #pragma unroll
    for (int i = 0; i < 4; i++)
        sh[(ty + 8 * i) * 33 + tx] = W[(size_t)(kb + ty + 8 * i) * N + nb + tx];
    __syncthreads();
    #pragma unroll
    for (int i = 0; i < 4; i++)
        Wt[(size_t)(nb + ty + 8 * i) * K + perm64h(kb + tx)] =
            __float2half_rn(sh[tx * 33 + ty + 8 * i]);
}

// ---------------------------------------------------------------------------
// Kernel 1: prep = ada (0..23) + rope (24..55) + W_qkv transpose (56..3127)
// ---------------------------------------------------------------------------
__global__ void __launch_bounds__(256) prep_kernel(
    const float* __restrict__ ctx, const float* __restrict__ W_ada,
    const float* __restrict__ b_ada, float* __restrict__ ada,
    float2* __restrict__ rope,
    const float* __restrict__ W_qkv, __half* __restrict__ wqkv)
{
    __shared__ float sh[8448];
    const int b = blockIdx.x;
    if (b < 24) {
        for (int i = threadIdx.x; i < 8192; i += 256) {
            float c = ctx[i];
            sh[i] = c / (1.f + __expf(-c));
        }
        __syncthreads();
        const int col = b * 256 + threadIdx.x;
        float acc[8] = {0, 0, 0, 0, 0, 0, 0, 0};
        for (int k = 0; k < 1024; k++) {
            float w = W_ada[(size_t)k * 6144 + col];
            #pragma unroll
            for (int bb = 0; bb < 8; bb++) acc[bb] += sh[bb * 1024 + k] * w;
        }
        float bv = b_ada[col];
        #pragma unroll
        for (int bb = 0; bb < 8; bb++) ada[bb * 6144 + col] = acc[bb] + bv;
    } else if (b < 56) {
        int idx = (b - 24) * 256 + threadIdx.x;
        if (idx < 8192) {
            int pos = idx >> 6;
            int i   = idx & 63;
            float freq = powf(10000.f, -(float)(2 * i) / 128.f);
            float ang  = (float)pos * freq;
            rope[idx] = make_float2(sinf(ang), cosf(ang));
        }
    } else {
        const int t = b - 56;
        const int nb = (t % 96) * 32;
        const int kb = (t / 96) * 32;
        dev_transpose(W_qkv, wqkv, 1024, 3072, kb, nb, sh);
    }
}

// ---------------------------------------------------------------------------
// Kernel 2: rmsnorm + modulate -> fp16 perm64 (+ weight transposes, norm1)
// ---------------------------------------------------------------------------
__global__ void __launch_bounds__(256) norm_mod(
    const float* __restrict__ x, const float* __restrict__ scale,
    const float* __restrict__ ada, int shOff, int scOff,
    __half* __restrict__ y,
    const float* __restrict__ W_out, __half* __restrict__ wout,
    const float* __restrict__ W_ff1, __half* __restrict__ wff1,
    const float* __restrict__ W_ff2, __half* __restrict__ wff2)
{
    __shared__ float sh[1056];
    const int row = blockIdx.x;
    if (row >= 32768) {
        int t = row - 32768;
        if (t < 1024) {
            dev_transpose(W_out, wout, 1024, 1024, (t / 32) * 32, (t % 32) * 32, sh);
        } else if (t < 5120) {
            t -= 1024;
            dev_transpose(W_ff1, wff1, 1024, 4096, (t / 128) * 32, (t % 128) * 32, sh);
        } else {
            t -= 5120;
            dev_transpose(W_ff2, wff2, 4096, 1024, (t / 32) * 32, (t % 32) * 32, sh);
        }
        return;
    }
    const int b = row >> 12;
    const float4 v = ((const float4*)(x + (size_t)row * 1024))[threadIdx.x];

    float ss = v.x * v.x + v.y * v.y + v.z * v.z + v.w * v.w;
    #pragma unroll
    for (int o = 16; o > 0; o >>= 1) ss += __shfl_xor_sync(0xffffffffu, ss, o);
    if ((threadIdx.x & 31) == 0) sh[threadIdx.x >> 5] = ss;
    __syncthreads();
    float tot = 0.f;
    #pragma unroll
    for (int i = 0; i < 8; i++) tot += sh[i];
    const float r = rsqrtf(tot * (1.f / 1024.f) + 1e-5f);

    const int c = threadIdx.x * 4;
    const float* ab = ada + b * 6144;
    const float4 s   = *(const float4*)(scale + c);
    const float4 shv = *(const float4*)(ab + shOff + c);
    const float4 scm = *(const float4*)(ab + scOff + c);
    float o0 = v.x * r * s.x * (1.f + scm.x) + shv.x;
    float o1 = v.y * r * s.y * (1.f + scm.y) + shv.y;
    float o2 = v.z * r * s.z * (1.f + scm.z) + shv.z;
    float o3 = v.w * r * s.w * (1.f + scm.w) + shv.w;
    __half* yr = y + (size_t)row * 1024;
    *(half2*)(yr + perm64c(c))     = __floats2half2_rn(o0, o1);
    *(half2*)(yr + perm64c(c + 2)) = __floats2half2_rn(o2, o3);
}

// ---------------------------------------------------------------------------
// Kernel 4: fp16 GEMM, CTA 128x256 (R13 config).
//   MODE 1: fp16-perm64 gelu. 2: fp32 res+gate*C. 3: fp16 natural.
// ---------------------------------------------------------------------------
#define STAGE_BYTES 49152
#define GEMM_SMEM  (3 * STAGE_BYTES)

template <int MODE>
__global__ void __launch_bounds__(256, 1) gemm_fp16(
    const __half* __restrict__ A, const __half* __restrict__ Bt,
    const float* __restrict__ bias,
    float* __restrict__ C, __half* __restrict__ Ch,
    int N, int K,
    const float* __restrict__ res, const float* __restrict__ gate)
{
    extern __shared__ char smem[];
    const uint32_t sm_u = smem_u32(smem);

    const int tid  = threadIdx.x;
    const int lane = tid & 31;
    const int warp = tid >> 5;
    const int g    = lane >> 2, tig = lane & 3;
    const int wm   = warp & 1;
    const int wn   = warp >> 1;
    const int cm   = blockIdx.y << 7;
    const int cn   = blockIdx.x << 8;
    const int KT   = K >> 6;

    const int f_row = tid >> 3;
    const int f_ch  = tid & 7;

    auto fill = [&](int kt, int s) {
        const uint32_t sb_ = sm_u + s * STAGE_BYTES;
        const __half* Ag = A + (size_t)(cm + f_row) * K + (kt << 6) + f_ch * 8;
        #pragma unroll
        for (int i = 0; i < 4; i++) {
            const int row = f_row + i * 32;
            cp16(sb_ + row * 128 + ((f_ch ^ (row & 7)) << 4),
                 Ag + (size_t)i * 32 * K);
        }
        const __half* Bg = Bt + (size_t)(cn + f_row) * K + (kt << 6) + f_ch * 8;
        #pragma unroll
        for (int i = 0; i < 8; i++) {
            const int row = f_row + i * 32;
            cp16(sb_ + 16384 + row * 128 + ((f_ch ^ (row & 7)) << 4),
                 Bg + (size_t)i * 32 * K);
        }
    };

    float acc[4][8][4];
    #pragma unroll
    for (int mt = 0; mt < 4; mt++)
        #pragma unroll
        for (int nt = 0; nt < 8; nt++)
            #pragma unroll
            for (int i = 0; i < 4; i++) acc[mt][nt][i] = 0.f;

    fill(0, 0); CP_COMMIT();
    if (KT > 1) fill(1, 1);
    CP_COMMIT();

    int s = 0;
    for (int kt = 0; kt < KT; kt++) {
        CP_WAIT1();
        __syncthreads();

        const uint32_t a_base = sm_u + s * STAGE_BYTES;
        const uint32_t b_base = a_base + 16384;
        #pragma unroll
        for (int sb = 0; sb < 2; sb++) {
            const int chn = (tig << 1) | sb;
            uint4 al[4], ah[4];
            #pragma unroll
            for (int mt = 0; mt < 4; mt++) {
                const int rl = wm * 64 + mt * 16 + g;
                al[mt] = lds128(a_base + rl * 128 + ((chn ^ (rl & 7)) << 4));
                ah[mt] = lds128(a_base + (rl + 8) * 128 + ((chn ^ (rl & 7)) << 4));
            }
            #pragma unroll
            for (int nt = 0; nt < 8; nt++) {
                const int rb = wn * 64 + nt * 8 + g;
                const uint4 bb = lds128(b_base + rb * 128 + ((chn ^ (rb & 7)) << 4));
                #pragma unroll
                for (int mt = 0; mt < 4; mt++) {
                    mma16(acc[mt][nt], al[mt].x, ah[mt].x, al[mt].y, ah[mt].y,
                          bb.x, bb.y);
                    mma16(acc[mt][nt], al[mt].z, ah[mt].z, al[mt].w, ah[mt].w,
                          bb.z, bb.w);
                }
            }
        }
        if (kt + 2 < KT) fill(kt + 2, (s + 2 >= 3) ? s - 1 : s + 2);
        CP_COMMIT();
        s = (s + 1 == 3) ? 0 : s + 1;
    }

    const int bb_i = cm >> 12;
    #pragma unroll
    for (int mt = 0; mt < 4; mt++) {
        const int row0 = cm + wm * 64 + mt * 16 + g;
        #pragma unroll
        for (int nt = 0; nt < 8; nt++) {
            const int col = cn + wn * 64 + nt * 8 + (tig << 1);
            const float bi0 = bias[col], bi1 = bias[col + 1];
            float v0 = acc[mt][nt][0] + bi0;
            float v1 = acc[mt][nt][1] + bi1;
            float v2 = acc[mt][nt][2] + bi0;
            float v3 = acc[mt][nt][3] + bi1;
            if (MODE == 1) {
                v0 = gelu_fast(v0); v1 = gelu_fast(v1);
                v2 = gelu_fast(v2); v3 = gelu_fast(v3);
                const int p = perm64c(col);
                *(half2*)(Ch + (size_t)row0 * N + p)       = __floats2half2_rn(v0, v1);
                *(half2*)(Ch + (size_t)(row0 + 8) * N + p) = __floats2half2_rn(v2, v3);
            } else if (MODE == 3) {
                *(half2*)(Ch + (size_t)row0 * N + col)       = __floats2half2_rn(v0, v1);
                *(half2*)(Ch + (size_t)(row0 + 8) * N + col) = __floats2half2_rn(v2, v3);
            } else {
                if (MODE == 2) {
                    const float g0 = gate[bb_i * 6144 + col];
                    const float g1 = gate[bb_i * 6144 + col + 1];
                    const float2 r0 = *(const float2*)(res + (size_t)row0 * N + col);
                    const float2 r1 = *(const float2*)(res + (size_t)(row0 + 8) * N + col);
                    v0 = r0.x + g0 * v0;  v1 = r0.y + g1 * v1;
                    v2 = r1.x + g0 * v2;  v3 = r1.y + g1 * v3;
                }
                *(float2*)(C + (size_t)row0 * N + col)       = make_float2(v0, v1);
                *(float2*)(C + (size_t)(row0 + 8) * N + col) = make_float2(v2, v3);
            }
        }
    }
}

// ---------------------------------------------------------------------------
// Kernel 5: persistent windowed attention (R13, launch #4)
// ---------------------------------------------------------------------------
#define AT_BUF  98304
#define ATTN_SMEM_BYTES AT_BUF
#define AT_NTILES 2048
#define AT_GRID   296

__global__ void __launch_bounds__(256, 2) attn_kernel(
    const __half* __restrict__ qkv, __half* __restrict__ obuf,
    const float2* __restrict__ rope)
{
    extern __shared__ char sha[];
    const uint32_t sm_u = smem_u32(sha);

    const int tid  = threadIdx.x;
    const int lane = tid & 31, warp = tid >> 5;
    const int tig  = lane & 3;

    const int s_row = tid >> 4, s_ch = tid & 15;

    auto stage = [&](int tile) {
        const int w = tile >> 3, h = tile & 7;
        const size_t rb = (size_t)w * 128;
        const __half* base = qkv + (rb + s_row) * 3072 + h * 128 + s_ch * 8;
        #pragma unroll
        for (int i = 0; i < 8; i++) {
            const int r = s_row + i * 16;
            const uint32_t off = r * 256 + ((s_ch ^ (r & 7)) << 4);
            const __half* src = base + (size_t)i * 16 * 3072;
            cp16(sm_u + off,         src);
            cp16(sm_u + 32768 + off, src + 1024);
            cp16(sm_u + 65536 + off, src + 2048);
        }
    };

    const int m0 = warp * 16;
    const int l7 = lane & 7;
    const int a_row = m0 + l7 + ((lane & 8) ? 8 : 0);
    const int a_kc8 = (lane & 16) ? 1 : 0;
    const int b_row = l7 + ((lane & 16) ? 8 : 0);
    const int b_kc8 = (lane & 8) ? 1 : 0;
    const int v_row = l7 + ((lane & 8) ? 8 : 0);
    const int v_dc8 = (lane & 16) ? 1 : 0;

    const uint32_t q_u = sm_u;
    const uint32_t k_u = sm_u + 32768;
    const uint32_t v_u = sm_u + 65536;

    stage(blockIdx.x); CP_COMMIT();

    for (int tile = blockIdx.x; tile < AT_NTILES; tile += AT_GRID) {
        CP_WAIT0();
        __syncthreads();

        const int h = tile & 7;
        const size_t rowbase = (size_t)(tile >> 3) * 128;

        #pragma unroll
        for (int it = 0; it < 16; it++) {
            const int task = tid + it * 256;
            const int i  = task >> 5;
            const int dp = task & 31;
            const int d  = dp << 1;
            const int clo = (d >> 3) ^ (i & 7);
            const int chi = ((d + 64) >> 3) ^ (i & 7);
            const int ib  = (d << 1) & 15;
            const uint32_t lo = i * 256 + (clo << 4) + ib;
            const uint32_t hi = i * 256 + (chi << 4) + ib;
            const float2 sc_lo = rope[i * 64 + dp];
            const float2 sc_hi = rope[i * 64 + dp + 32];
            {
                half2* plo = (half2*)(sha + lo);
                half2* phi = (half2*)(sha + hi);
                float2 a = __half22float2(*plo);
                float2 b = __half22float2(*phi);
                *plo = __floats2half2_rn(a.x * sc_lo.y - b.x * sc_lo.x,
                                         a.y * sc_lo.y - b.y * sc_lo.x);
                *phi = __floats2half2_rn(b.x * sc_hi.y + a.x * sc_hi.x,
                                         b.y * sc_hi.y + a.y * sc_hi.x);
            }
            {
                half2* plo = (half2*)(sha + 32768 + lo);
                half2* phi = (half2*)(sha + 32768 + hi);
                float2 a = __half22float2(*plo);
                float2 b = __half22float2(*phi);
                *plo = __floats2half2_rn(a.x * sc_lo.y - b.x * sc_lo.x,
                                         a.y * sc_lo.y - b.y * sc_lo.x);
                *phi = __floats2half2_rn(b.x * sc_hi.y + a.x * sc_hi.x,
                                         b.y * sc_hi.y + a.y * sc_hi.x);
            }
        }
        __syncthreads();

        float acc[16][4];
        #pragma unroll
        for (int nt = 0; nt < 16; nt++)
            #pragma unroll
            for (int i = 0; i < 4; i++) acc[nt][i] = 0.f;

        #pragma unroll
        for (int kc = 0; kc < 8; kc++) {
            uint32_t a0, a1, a2, a3;
            const int ca = (kc * 2 + a_kc8) ^ (a_row & 7);
            ldsm_x4(a0, a1, a2, a3, q_u + a_row * 256 + (ca << 4));
            #pragma unroll
            for (int np = 0; np < 8; np++) {
                const int row = np * 16 + b_row;
                const int cb = (kc * 2 + b_kc8) ^ (row & 7);
                uint32_t b0, b1, c0, c1;
                ldsm_x4(b0, b1, c0, c1, k_u + row * 256 + (cb << 4));
                mma16(acc[2 * np],     a0, a1, a2, a3, b0, b1);
                mma16(acc[2 * np + 1], a0, a1, a2, a3, c0, c1);
            }
        }

        const float scl = 0.08838834764831845f;
        float mx0 = -1e30f, mx1 = -1e30f;
        #pragma unroll
        for (int nt = 0; nt < 16; nt++) {
            acc[nt][0] *= scl; acc[nt][1] *= scl;
            acc[nt][2] *= scl; acc[nt][3] *= scl;
            mx0 = fmaxf(mx0, fmaxf(acc[nt][0], acc[nt][1]));
            mx1 = fmaxf(mx1, fmaxf(acc[nt][2], acc[nt][3]));
        }
        mx0 = fmaxf(mx0, __shfl_xor_sync(0xffffffffu, mx0, 1));
        mx0 = fmaxf(mx0, __shfl_xor_sync(0xffffffffu, mx0, 2));
        mx1 = fmaxf(mx1, __shfl_xor_sync(0xffffffffu, mx1, 1));
        mx1 = fmaxf(mx1, __shfl_xor_sync(0xffffffffu, mx1, 2));

        float s0 = 0.f, s1 = 0.f;
        #pragma unroll
        for (int nt = 0; nt < 16; nt++) {
            acc[nt][0] = __expf(acc[nt][0] - mx0);
            acc[nt][1] = __expf(acc[nt][1] - mx0);
            acc[nt][2] = __expf(acc[nt][2] - mx1);
            acc[nt][3] = __expf(acc[nt][3] - mx1);
            s0 += acc[nt][0] + acc[nt][1];
            s1 += acc[nt][2] + acc[nt][3];
        }
        s0 += __shfl_xor_sync(0xffffffffu, s0, 1);
        s0 += __shfl_xor_sync(0xffffffffu, s0, 2);
        s1 += __shfl_xor_sync(0xffffffffu, s1, 1);
        s1 += __shfl_xor_sync(0xffffffffu, s1, 2);
        const float i0 = 1.f / s0, i1 = 1.f / s1;

        uint32_t p[32];
        #pragma unroll
        for (int kc = 0; kc < 8; kc++) {
            p[4 * kc + 0] = h2u(__floats2half2_rn(acc[2 * kc][0] * i0, acc[2 * kc][1] * i0));
            p[4 * kc + 1] = h2u(__floats2half2_rn(acc[2 * kc][2] * i1, acc[2 * kc][3] * i1));
            p[4 * kc + 2] = h2u(__floats2half2_rn(acc[2 * kc + 1][0] * i0, acc[2 * kc + 1][1] * i0));
            p[4 * kc + 3] = h2u(__floats2half2_rn(acc[2 * kc + 1][2] * i1, acc[2 * kc + 1][3] * i1));
        }

        float o[16][4];
        #pragma unroll
        for (int nt = 0; nt < 16; nt++)
            #pragma unroll
            for (int i = 0; i < 4; i++) o[nt][i] = 0.f;

        #pragma unroll
        for (int kc = 0; kc < 8; kc++) {
            #pragma unroll
            for (int dp = 0; dp < 8; dp++) {
                const int row = kc * 16 + v_row;
                const int cv = (dp * 2 + v_dc8) ^ (row & 7);
                uint32_t b0, b1, c0, c1;
                ldsm_x4t(b0, b1, c0, c1, v_u + row * 256 + (cv << 4));
                mma16(o[2 * dp],     p[4 * kc], p[4 * kc + 1], p[4 * kc + 2], p[4 * kc + 3], b0, b1);
                mma16(o[2 * dp + 1], p[4 * kc], p[4 * kc + 1], p[4 * kc + 2], p[4 * kc + 3], c0, c1);
            }
        }

        __syncthreads();
        if (tile + AT_GRID < AT_NTILES) stage(tile + AT_GRID);
        CP_COMMIT();

        const int gq = lane >> 2;
        #pragma unroll
        for (int nt = 0; nt < 16; nt++) {
            const int col = h * 128 + nt * 8 + (tig << 1);
            const int pc = perm64c(col);
            *(half2*)(obuf + (rowbase + m0 + gq) * 1024 + pc) =
                __floats2half2_rn(o[nt][0], o[nt][1]);
            *(half2*)(obuf + (rowbase + m0 + gq + 8) * 1024 + pc) =
                __floats2half2_rn(o[nt][2], o[nt][3]);
        }
    }
}

// ---------------------------------------------------------------------------
// host launcher — 8 launches; attention is #4 (profiled by ncu)
// ---------------------------------------------------------------------------
extern "C" void kernel_launch(void* const* d_in, const int* in_sizes, int n_in,
                              void* d_out, int out_size)
{
    const float* group_x = (const float*)d_in[0];
    const float* context = (const float*)d_in[1];
    const float* W_ada   = (const float*)d_in[2];
    const float* b_ada   = (const float*)d_in[3];
    const float* scale1  = (const float*)d_in[4];
    const float* W_qkv   = (const float*)d_in[5];
    const float* b_qkv   = (const float*)d_in[6];
    const float* W_out   = (const float*)d_in[7];
    const float* b_out   = (const float*)d_in[8];
    const float* scale2  = (const float*)d_in[9];
    const float* W_ff1   = (const float*)d_in[10];
    const float* b_ff1   = (const float*)d_in[11];
    const float* W_ff2   = (const float*)d_in[12];
    const float* b_ff2   = (const float*)d_in[13];
    float* out = (float*)d_out;

    float *ada, *res2;
    __half *x1, *qkv, *obuf, *hbuf, *h1, *wqkv, *wout, *wff1, *wff2;
    float2* rope;
    cudaGetSymbolAddress((void**)&ada,  g_ada);
    cudaGetSymbolAddress((void**)&x1,   g_x1);
    cudaGetSymbolAddress((void**)&qkv,  g_qkv);
    cudaGetSymbolAddress((void**)&obuf, g_o);
    cudaGetSymbolAddress((void**)&res2, g_res);
    cudaGetSymbolAddress((void**)&hbuf, g_h);
    cudaGetSymbolAddress((void**)&h1,   g_h1);
    cudaGetSymbolAddress((void**)&rope, g_rope);
    cudaGetSymbolAddress((void**)&wqkv, g_wqkv);
    cudaGetSymbolAddress((void**)&wout, g_wout);
    cudaGetSymbolAddress((void**)&wff1, g_wff1);
    cudaGetSymbolAddress((void**)&wff2, g_wff2);

    cudaFuncSetAttribute(gemm_fp16<1>, cudaFuncAttributeMaxDynamicSharedMemorySize, GEMM_SMEM);
    cudaFuncSetAttribute(gemm_fp16<2>, cudaFuncAttributeMaxDynamicSharedMemorySize, GEMM_SMEM);
    cudaFuncSetAttribute(gemm_fp16<3>, cudaFuncAttributeMaxDynamicSharedMemorySize, GEMM_SMEM);
    cudaFuncSetAttribute(attn_kernel,  cudaFuncAttributeMaxDynamicSharedMemorySize, ATTN_SMEM_BYTES);

    // 1: ada + rope + W_qkv transpose
    prep_kernel<<<3128, 256>>>(context, W_ada, b_ada, ada, rope, W_qkv, wqkv);

    // 2: norm1 (+ wout/wff1/wff2 transposes in extra blocks)
    norm_mod<<<32768 + 9216, 256>>>(group_x, scale1, ada, 0, 1024, x1,
                                    W_out, wout, W_ff1, wff1, W_ff2, wff2);

    // 3: qkv = x1 @ W_qkv + b_qkv -> fp16 natural   (N=3072, K=1024)
    gemm_fp16<3><<<dim3(12, 256), 256, GEMM_SMEM>>>(x1, wqkv, b_qkv, nullptr, qkv,
                                                    3072, 1024, nullptr, nullptr);

    // 4 (profiled): persistent attention
    attn_kernel<<<AT_GRID, 256, ATTN_SMEM_BYTES>>>(qkv, obuf, rope);

    // 5: res2 = group_x + g_msa * (obuf @ W_out + b_out)   (N=1024, K=1024)
    gemm_fp16<2><<<dim3(4, 256), 256, GEMM_SMEM>>>(obuf, wout, b_out, res2, nullptr,
                                                   1024, 1024, group_x, ada + 2048);

    // 6: norm2
    norm_mod<<<32768, 256>>>(res2, scale2, ada, 3072, 4096, hbuf,
                             nullptr, nullptr, nullptr, nullptr, nullptr, nullptr);

    // 7: h1 = gelu(hbuf @ W_ff1 + b_ff1) -> fp16 perm64  (N=4096, K=1024)
    gemm_fp16<1><<<dim3(16, 256), 256, GEMM_SMEM>>>(hbuf, wff1, b_ff1, nullptr, h1,
                                                    4096, 1024, nullptr, nullptr);
    // 8: out = res2 + g_mlp * (h1 @ W_ff2 + b_ff2)        (N=1024, K=4096)
    gemm_fp16<2><<<dim3(4, 256), 256, GEMM_SMEM>>>(h1, wff2, b_ff2, out, nullptr,
                                                   1024, 4096, res2, ada + 5120);
}

// round 16
// speedup vs baseline: 1.0268x; 1.0040x over previous
#include <cuda_runtime.h>
#include <cuda_fp16.h>
#include <cstdint>

// ---------------------------------------------------------------------------
// B=8, L=4096, D=1024, H=8, DH=128, WIN=128; M = 32768.
// GEMMs: mma.sync m16n8k16 fp16 fp32-acc, CTA 128x256, BK=128, 2-stage
// cp.async (196KB smem) — halved barrier rounds vs R15. GELU via sigmoid
// identity. Attention: persistent 296 CTAs (launch #4, profiled).
// ---------------------------------------------------------------------------

__device__ float  g_ada [8 * 6144];
__device__ __half g_x1  [33554432];
__device__ __half g_qkv [100663296];
__device__ __half g_o   [33554432];
__device__ float  g_res [33554432];
__device__ __half g_h   [33554432];
__device__ __half g_h1  [134217728];
__device__ float2 g_rope[8192];
__device__ __half g_wqkv[3145728];
__device__ __half g_wout[1048576];
__device__ __half g_wff1[4194304];
__device__ __half g_wff2[4194304];

// ---------------------------------------------------------------------------
// helpers
// ---------------------------------------------------------------------------
__device__ __forceinline__ float gelu_fast(float x) {
    const float t = 1.5957691216057308f * (x + 0.044715f * x * x * x);
    return __fdividef(x, 1.f + __expf(-t));
}

__device__ __forceinline__ uint32_t smem_u32(const void* p) {
    uint32_t a;
    asm("{ .reg .u64 t; cvta.to.shared.u64 t, %1; cvt.u32.u64 %0, t; }" : "=r"(a) : "l"(p));
    return a;
}

__device__ __forceinline__ uint32_t h2u(half2 h) {
    uint32_t u;
    memcpy(&u, &h, 4);
    return u;
}

// perm64 operand layout: applied to BOTH A and B k-dims (dot-product invariant)
__device__ __forceinline__ int perm64h(int k) {
    const int base  = k & ~63;
    const int sb    = (k >> 5) & 1;
    const int b16   = (k >> 4) & 1;
    const int j     = (k & 15) >> 1;
    const int owner = j & 3, hi = j >> 2;
    return base + (owner * 2 + sb) * 8 + b16 * 4 + hi * 2 + (k & 1);
}
__device__ __forceinline__ int perm64c(int col) { return perm64h(col); }

__device__ __forceinline__ void mma16(float* d, uint32_t a0, uint32_t a1,
                                      uint32_t a2, uint32_t a3,
                                      uint32_t b0, uint32_t b1) {
    asm volatile(
        "mma.sync.aligned.m16n8k16.row.col.f32.f16.f16.f32 "
        "{%0,%1,%2,%3}, {%4,%5,%6,%7}, {%8,%9}, {%0,%1,%2,%3};"
        : "+f"(d[0]), "+f"(d[1]), "+f"(d[2]), "+f"(d[3])
        : "r"(a0), "r"(a1), "r"(a2), "r"(a3), "r"(b0), "r"(b1));
}

__device__ __forceinline__ void ldsm_x4(uint32_t& r0, uint32_t& r1,
                                        uint32_t& r2, uint32_t& r3, uint32_t a) {
    asm volatile("ldmatrix.sync.aligned.m8n8.x4.shared.b16 {%0,%1,%2,%3}, [%4];"
                 : "=r"(r0), "=r"(r1), "=r"(r2), "=r"(r3) : "r"(a));
}
__device__ __forceinline__ void ldsm_x4t(uint32_t& r0, uint32_t& r1,
                                         uint32_t& r2, uint32_t& r3, uint32_t a) {
    asm volatile("ldmatrix.sync.aligned.m8n8.x4.trans.shared.b16 {%0,%1,%2,%3}, [%4];"
                 : "=r"(r0), "=r"(r1), "=r"(r2), "=r"(r3) : "r"(a));
}

__device__ __forceinline__ uint4 lds128(uint32_t a) {
    uint4 v;
    asm volatile("ld.shared.v4.u32 {%0,%1,%2,%3}, [%4];"
                 : "=r"(v.x), "=r"(v.y), "=r"(v.z), "=r"(v.w) : "r"(a));
    return v;
}

__device__ __forceinline__ void cp16(uint32_t dst, const void* src) {
    asm volatile("cp.async.cg.shared.global [%0], [%1], 16;" :: "r"(dst), "l"(src));
}
#define CP_COMMIT() asm volatile("cp.async.commit_group;" ::: "memory")
#define CP_WAIT1()  asm volatile("cp.async.wait_group 1;"  ::: "memory")
#define CP_WAIT0()  asm volatile("cp.async.wait_group 0;"  ::: "memory")

// ---------------------------------------------------------------------------
// device transpose helper: Wt[n][perm64(k)] = fp16(W[k][n]), 32x32 tile
// ---------------------------------------------------------------------------
__device__ __forceinline__ void dev_transpose(
    const float* __restrict__ W, __half* __restrict__ Wt,
    int K, int N, int kb, int nb, float* sh)
{
    const int tx = threadIdx.x & 31, ty = threadIdx.x >> 5;   // 32 x 8
    #pragma unroll
    for (int i = 0; i < 4; i++)
        sh[(ty + 8 * i) * 33 + tx] = W[(size_t)(kb + ty + 8 * i) * N + nb + tx];
    __syncthreads();
    #pragma unroll
    for (int i = 0; i < 4; i++)
        Wt[(size_t)(nb + ty + 8 * i) * K + perm64h(kb + tx)] =
            __float2half_rn(sh[tx * 33 + ty + 8 * i]);
}

// ---------------------------------------------------------------------------
// Kernel 1: prep = ada (0..23) + rope (24..55) + W_qkv transpose (56..3127)
// ---------------------------------------------------------------------------
__global__ void __launch_bounds__(256) prep_kernel(
    const float* __restrict__ ctx, const float* __restrict__ W_ada,
    const float* __restrict__ b_ada, float* __restrict__ ada,
    float2* __restrict__ rope,
    const float* __restrict__ W_qkv, __half* __restrict__ wqkv)
{
    __shared__ float sh[8448];
    const int b = blockIdx.x;
    if (b < 24) {
        for (int i = threadIdx.x; i < 8192; i += 256) {
            float c = ctx[i];
            sh[i] = c / (1.f + __expf(-c));
        }
        __syncthreads();
        const int col = b * 256 + threadIdx.x;
        float acc[8] = {0, 0, 0, 0, 0, 0, 0, 0};
        for (int k = 0; k < 1024; k++) {
            float w = W_ada[(size_t)k * 6144 + col];
            #pragma unroll
            for (int bb = 0; bb < 8; bb++) acc[bb] += sh[bb * 1024 + k] * w;
        }
        float bv = b_ada[col];
        #pragma unroll
        for (int bb = 0; bb < 8; bb++) ada[bb * 6144 + col] = acc[bb] + bv;
    } else if (b < 56) {
        int idx = (b - 24) * 256 + threadIdx.x;
        if (idx < 8192) {
            int pos = idx >> 6;
            int i   = idx & 63;
            float freq = powf(10000.f, -(float)(2 * i) / 128.f);
            float ang  = (float)pos * freq;
            rope[idx] = make_float2(sinf(ang), cosf(ang));
        }
    } else {
        const int t = b - 56;
        const int nb = (t % 96) * 32;
        const int kb = (t / 96) * 32;
        dev_transpose(W_qkv, wqkv, 1024, 3072, kb, nb, sh);
    }
}

// ---------------------------------------------------------------------------
// Kernel 2: rmsnorm + modulate -> fp16 perm64 (+ weight transposes, norm1)
// ---------------------------------------------------------------------------
__global__ void __launch_bounds__(256) norm_mod(
    const float* __restrict__ x, const float* __restrict__ scale,
    const float* __restrict__ ada, int shOff, int scOff,
    __half* __restrict__ y,
    const float* __restrict__ W_out, __half* __restrict__ wout,
    const float* __restrict__ W_ff1, __half* __restrict__ wff1,
    const float* __restrict__ W_ff2, __half* __restrict__ wff2)
{
    __shared__ float sh[1056];
    const int row = blockIdx.x;
    if (row >= 32768) {
        int t = row - 32768;
        if (t < 1024) {
            dev_transpose(W_out, wout, 1024, 1024, (t / 32) * 32, (t % 32) * 32, sh);
        } else if (t < 5120) {
            t -= 1024;
            dev_transpose(W_ff1, wff1, 1024, 4096, (t / 128) * 32, (t % 128) * 32, sh);
        } else {
            t -= 5120;
            dev_transpose(W_ff2, wff2, 4096, 1024, (t / 32) * 32, (t % 32) * 32, sh);
        }
        return;
    }
    const int b = row >> 12;
    const float4 v = ((const float4*)(x + (size_t)row * 1024))[threadIdx.x];

    float ss = v.x * v.x + v.y * v.y + v.z * v.z + v.w * v.w;
    #pragma unroll
    for (int o = 16; o > 0; o >>= 1) ss += __shfl_xor_sync(0xffffffffu, ss, o);
    if ((threadIdx.x & 31) == 0) sh[threadIdx.x >> 5] = ss;
    __syncthreads();
    float tot = 0.f;
    #pragma unroll
    for (int i = 0; i < 8; i++) tot += sh[i];
    const float r = rsqrtf(tot * (1.f / 1024.f) + 1e-5f);

    const int c = threadIdx.x * 4;
    const float* ab = ada + b * 6144;
    const float4 s   = *(const float4*)(scale + c);
    const float4 shv = *(const float4*)(ab + shOff + c);
    const float4 scm = *(const float4*)(ab + scOff + c);
    float o0 = v.x * r * s.x * (1.f + scm.x) + shv.x;
    float o1 = v.y * r * s.y * (1.f + scm.y) + shv.y;
    float o2 = v.z * r * s.z * (1.f + scm.z) + shv.z;
    float o3 = v.w * r * s.w * (1.f + scm.w) + shv.w;
    __half* yr = y + (size_t)row * 1024;
    *(half2*)(yr + perm64c(c))     = __floats2half2_rn(o0, o1);
    *(half2*)(yr + perm64c(c + 2)) = __floats2half2_rn(o2, o3);
}

// ---------------------------------------------------------------------------
// Kernel 4: fp16 GEMM, CTA 128x256, BK=128, 2-stage (196KB smem).
//   Row = 256B = 16 chunks; swizzle chunk^(row&7) within 8-chunk halves.
//   MODE 1: fp16-perm64 gelu. 2: fp32 res+gate*C. 3: fp16 natural.
// ---------------------------------------------------------------------------
#define STAGE_BYTES 98304            // A: 128*256B + B: 256*256B
#define GEMM_SMEM  (2 * STAGE_BYTES) // 196608

template <int MODE>
__global__ void __launch_bounds__(256, 1) gemm_fp16(
    const __half* __restrict__ A, const __half* __restrict__ Bt,
    const float* __restrict__ bias,
    float* __restrict__ C, __half* __restrict__ Ch,
    int N, int K,
    const float* __restrict__ res, const float* __restrict__ gate)
{
    extern __shared__ char smem[];
    const uint32_t sm_u = smem_u32(smem);

    const int tid  = threadIdx.x;
    const int lane = tid & 31;
    const int warp = tid >> 5;
    const int g    = lane >> 2, tig = lane & 3;
    const int wm   = warp & 1;
    const int wn   = warp >> 1;
    const int cm   = blockIdx.y << 7;
    const int cn   = blockIdx.x << 8;
    const int KT   = K >> 7;

    // staging: chunk pos = tid & 15 (constant), row base = tid >> 4
    const int f_row = tid >> 4;          // 0..15
    const int f_pos = tid & 15;          // 0..15

    auto fill = [&](int kt, int s) {
        const uint32_t sb_ = sm_u + s * STAGE_BYTES;
        const __half* Ag = A + (size_t)(cm + f_row) * K + (kt << 7) + f_pos * 8;
        #pragma unroll
        for (int i = 0; i < 8; i++) {
            const int row = f_row + i * 16;
            cp16(sb_ + row * 256 + (((f_pos & 7) ^ (row & 7)) << 4) + ((f_pos & 8) << 4),
                 Ag + (size_t)i * 16 * K);
        }
        const __half* Bg = Bt + (size_t)(cn + f_row) * K + (kt << 7) + f_pos * 8;
        #pragma unroll
        for (int i = 0; i < 16; i++) {
            const int row = f_row + i * 16;
            cp16(sb_ + 32768 + row * 256 + (((f_pos & 7) ^ (row & 7)) << 4) + ((f_pos & 8) << 4),
                 Bg + (size_t)i * 16 * K);
        }
    };

    float acc[4][8][4];
    #pragma unroll
    for (int mt = 0; mt < 4; mt++)
        #pragma unroll
        for (int nt = 0; nt < 8; nt++)
            #pragma unroll
            for (int i = 0; i < 4; i++) acc[mt][nt][i] = 0.f;

    fill(0, 0); CP_COMMIT();

    for (int kt = 0; kt < KT; kt++) {
        const int buf = kt & 1;
        if (kt + 1 < KT) { fill(kt + 1, buf ^ 1); CP_COMMIT(); CP_WAIT1(); }
        else             { CP_WAIT0(); }
        __syncthreads();

        const uint32_t a_base = sm_u + buf * STAGE_BYTES;
        const uint32_t b_base = a_base + 32768;
        #pragma unroll
        for (int sb = 0; sb < 4; sb++) {
            const int half64 = sb >> 1;                 // 0..1: which 64-half block
            const int chn    = (tig << 1) | (sb & 1);   // 0..7 within block
            const int coff   = half64 << 7;             // +128B for second block
            uint4 al[4], ah[4];
            #pragma unroll
            for (int mt = 0; mt < 4; mt++) {
                const int rl = wm * 64 + mt * 16 + g;
                al[mt] = lds128(a_base + rl * 256 + coff + ((chn ^ (rl & 7)) << 4));
                ah[mt] = lds128(a_base + (rl + 8) * 256 + coff + ((chn ^ (rl & 7)) << 4));
            }
            #pragma unroll
            for (int nt = 0; nt < 8; nt++) {
                const int rb = wn * 64 + nt * 8 + g;
                const uint4 bb = lds128(b_base + rb * 256 + coff + ((chn ^ (rb & 7)) << 4));
                #pragma unroll
                for (int mt = 0; mt < 4; mt++) {
                    mma16(acc[mt][nt], al[mt].x, ah[mt].x, al[mt].y, ah[mt].y,
                          bb.x, bb.y);
                    mma16(acc[mt][nt], al[mt].z, ah[mt].z, al[mt].w, ah[mt].w,
                          bb.z, bb.w);
                }
            }
        }
        __syncthreads();
    }

    const int bb_i = cm >> 12;
    #pragma unroll
    for (int mt = 0; mt < 4; mt++) {
        const int row0 = cm + wm * 64 + mt * 16 + g;
        #pragma unroll
        for (int nt = 0; nt < 8; nt++) {
            const int col = cn + wn * 64 + nt * 8 + (tig << 1);
            const float bi0 = bias[col], bi1 = bias[col + 1];
            float v0 = acc[mt][nt][0] + bi0;
            float v1 = acc[mt][nt][1] + bi1;
            float v2 = acc[mt][nt][2] + bi0;
            float v3 = acc[mt][nt][3] + bi1;
            if (MODE == 1) {
                v0 = gelu_fast(v0); v1 = gelu_fast(v1);
                v2 = gelu_fast(v2); v3 = gelu_fast(v3);
                const int p = perm64c(col);
                *(half2*)(Ch + (size_t)row0 * N + p)       = __floats2half2_rn(v0, v1);
                *(half2*)(Ch + (size_t)(row0 + 8) * N + p) = __floats2half2_rn(v2, v3);
            } else if (MODE == 3) {
                *(half2*)(Ch + (size_t)row0 * N + col)       = __floats2half2_rn(v0, v1);
                *(half2*)(Ch + (size_t)(row0 + 8) * N + col) = __floats2half2_rn(v2, v3);
            } else {
                if (MODE == 2) {
                    const float g0 = gate[bb_i * 6144 + col];
                    const float g1 = gate[bb_i * 6144 + col + 1];
                    const float2 r0 = *(const float2*)(res + (size_t)row0 * N + col);
                    const float2 r1 = *(const float2*)(res + (size_t)(row0 + 8) * N + col);
                    v0 = r0.x + g0 * v0;  v1 = r0.y + g1 * v1;
                    v2 = r1.x + g0 * v2;  v3 = r1.y + g1 * v3;
                }
                *(float2*)(C + (size_t)row0 * N + col)       = make_float2(v0, v1);
                *(float2*)(C + (size_t)(row0 + 8) * N + col) = make_float2(v2, v3);
            }
        }
    }
}

// ---------------------------------------------------------------------------
// Kernel 5: persistent windowed attention (R15, launch #4)
// ---------------------------------------------------------------------------
#define AT_BUF  98304
#define ATTN_SMEM_BYTES AT_BUF
#define AT_NTILES 2048
#define AT_GRID   296

__global__ void __launch_bounds__(256, 2) attn_kernel(
    const __half* __restrict__ qkv, __half* __restrict__ obuf,
    const float2* __restrict__ rope)
{
    extern __shared__ char sha[];
    const uint32_t sm_u = smem_u32(sha);

    const int tid  = threadIdx.x;
    const int lane = tid & 31, warp = tid >> 5;
    const int tig  = lane & 3;

    const int s_row = tid >> 4, s_ch = tid & 15;

    auto stage = [&](int tile) {
        const int w = tile >> 3, h = tile & 7;
        const size_t rb = (size_t)w * 128;
        const __half* base = qkv + (rb + s_row) * 3072 + h * 128 + s_ch * 8;
        #pragma unroll
        for (int i = 0; i < 8; i++) {
            const int r = s_row + i * 16;
            const uint32_t off = r * 256 + ((s_ch ^ (r & 7)) << 4);
            const __half* src = base + (size_t)i * 16 * 3072;
            cp16(sm_u + off,         src);
            cp16(sm_u + 32768 + off, src + 1024);
            cp16(sm_u + 65536 + off, src + 2048);
        }
    };

    const int m0 = warp * 16;
    const int l7 = lane & 7;
    const int a_row = m0 + l7 + ((lane & 8) ? 8 : 0);
    const int a_kc8 = (lane & 16) ? 1 : 0;
    const int b_row = l7 + ((lane & 16) ? 8 : 0);
    const int b_kc8 = (lane & 8) ? 1 : 0;
    const int v_row = l7 + ((lane & 8) ? 8 : 0);
    const int v_dc8 = (lane & 16) ? 1 : 0;

    const uint32_t q_u = sm_u;
    const uint32_t k_u = sm_u + 32768;
    const uint32_t v_u = sm_u + 65536;

    stage(blockIdx.x); CP_COMMIT();

    for (int tile = blockIdx.x; tile < AT_NTILES; tile += AT_GRID) {
        CP_WAIT0();
        __syncthreads();

        const int h = tile & 7;
        const size_t rowbase = (size_t)(tile >> 3) * 128;

        #pragma unroll
        for (int it = 0; it < 16; it++) {
            const int task = tid + it * 256;
            const int i  = task >> 5;
            const int dp = task & 31;
            const int d  = dp << 1;
            const int clo = (d >> 3) ^ (i & 7);
            const int chi = ((d + 64) >> 3) ^ (i & 7);
            const int ib  = (d << 1) & 15;
            const uint32_t lo = i * 256 + (clo << 4) + ib;
            const uint32_t hi = i * 256 + (chi << 4) + ib;
            const float2 sc_lo = rope[i * 64 + dp];
            const float2 sc_hi = rope[i * 64 + dp + 32];
            {
                half2* plo = (half2*)(sha + lo);
                half2* phi = (half2*)(sha + hi);
                float2 a = __half22float2(*plo);
                float2 b = __half22float2(*phi);
                *plo = __floats2half2_rn(a.x * sc_lo.y - b.x * sc_lo.x,
                                         a.y * sc_lo.y - b.y * sc_lo.x);
                *phi = __floats2half2_rn(b.x * sc_hi.y + a.x * sc_hi.x,
                                         b.y * sc_hi.y + a.y * sc_hi.x);
            }
            {
                half2* plo = (half2*)(sha + 32768 + lo);
                half2* phi = (half2*)(sha + 32768 + hi);
                float2 a = __half22float2(*plo);
                float2 b = __half22float2(*phi);
                *plo = __floats2half2_rn(a.x * sc_lo.y - b.x * sc_lo.x,
                                         a.y * sc_lo.y - b.y * sc_lo.x);
                *phi = __floats2half2_rn(b.x * sc_hi.y + a.x * sc_hi.x,
                                         b.y * sc_hi.y + a.y * sc_hi.x);
            }
        }
        __syncthreads();

        float acc[16][4];
        #pragma unroll
        for (int nt = 0; nt < 16; nt++)
            #pragma unroll
            for (int i = 0; i < 4; i++) acc[nt][i] = 0.f;

        #pragma unroll
        for (int kc = 0; kc < 8; kc++) {
            uint32_t a0, a1, a2, a3;
            const int ca = (kc * 2 + a_kc8) ^ (a_row & 7);
            ldsm_x4(a0, a1, a2, a3, q_u + a_row * 256 + (ca << 4));
            #pragma unroll
            for (int np = 0; np < 8; np++) {
                const int row = np * 16 + b_row;
                const int cb = (kc * 2 + b_kc8) ^ (row & 7);
                uint32_t b0, b1, c0, c1;
                ldsm_x4(b0, b1, c0, c1, k_u + row * 256 + (cb << 4));
                mma16(acc[2 * np],     a0, a1, a2, a3, b0, b1);
                mma16(acc[2 * np + 1], a0, a1, a2, a3, c0, c1);
            }
        }

        const float scl = 0.08838834764831845f;
        float mx0 = -1e30f, mx1 = -1e30f;
        #pragma unroll
        for (int nt = 0; nt < 16; nt++) {
            acc[nt][0] *= scl; acc[nt][1] *= scl;
            acc[nt][2] *= scl; acc[nt][3] *= scl;
            mx0 = fmaxf(mx0, fmaxf(acc[nt][0], acc[nt][1]));
            mx1 = fmaxf(mx1, fmaxf(acc[nt][2], acc[nt][3]));
        }
        mx0 = fmaxf(mx0, __shfl_xor_sync(0xffffffffu, mx0, 1));
        mx0 = fmaxf(mx0, __shfl_xor_sync(0xffffffffu, mx0, 2));
        mx1 = fmaxf(mx1, __shfl_xor_sync(0xffffffffu, mx1, 1));
        mx1 = fmaxf(mx1, __shfl_xor_sync(0xffffffffu, mx1, 2));

        float s0 = 0.f, s1 = 0.f;
        #pragma unroll
        for (int nt = 0; nt < 16; nt++) {
            acc[nt][0] = __expf(acc[nt][0] - mx0);
            acc[nt][1] = __expf(acc[nt][1] - mx0);
            acc[nt][2] = __expf(acc[nt][2] - mx1);
            acc[nt][3] = __expf(acc[nt][3] - mx1);
            s0 += acc[nt][0] + acc[nt][1];
            s1 += acc[nt][2] + acc[nt][3];
        }
        s0 += __shfl_xor_sync(0xffffffffu, s0, 1);
        s0 += __shfl_xor_sync(0xffffffffu, s0, 2);
        s1 += __shfl_xor_sync(0xffffffffu, s1, 1);
        s1 += __shfl_xor_sync(0xffffffffu, s1, 2);
        const float i0 = 1.f / s0, i1 = 1.f / s1;

        uint32_t p[32];
        #pragma unroll
        for (int kc = 0; kc < 8; kc++) {
            p[4 * kc + 0] = h2u(__floats2half2_rn(acc[2 * kc][0] * i0, acc[2 * kc][1] * i0));
            p[4 * kc + 1] = h2u(__floats2half2_rn(acc[2 * kc][2] * i1, acc[2 * kc][3] * i1));
            p[4 * kc + 2] = h2u(__floats2half2_rn(acc[2 * kc + 1][0] * i0, acc[2 * kc + 1][1] * i0));
            p[4 * kc + 3] = h2u(__floats2half2_rn(acc[2 * kc + 1][2] * i1, acc[2 * kc + 1][3] * i1));
        }

        float o[16][4];
        #pragma unroll
        for (int nt = 0; nt < 16; nt++)
            #pragma unroll
            for (int i = 0; i < 4; i++) o[nt][i] = 0.f;

        #pragma unroll
        for (int kc = 0; kc < 8; kc++) {
            #pragma unroll
            for (int dp = 0; dp < 8; dp++) {
                const int row = kc * 16 + v_row;
                const int cv = (dp * 2 + v_dc8) ^ (row & 7);
                uint32_t b0, b1, c0, c1;
                ldsm_x4t(b0, b1, c0, c1, v_u + row * 256 + (cv << 4));
                mma16(o[2 * dp],     p[4 * kc], p[4 * kc + 1], p[4 * kc + 2], p[4 * kc + 3], b0, b1);
                mma16(o[2 * dp + 1], p[4 * kc], p[4 * kc + 1], p[4 * kc + 2], p[4 * kc + 3], c0, c1);
            }
        }

        __syncthreads();
        if (tile + AT_GRID < AT_NTILES) stage(tile + AT_GRID);
        CP_COMMIT();

        const int gq = lane >> 2;
        #pragma unroll
        for (int nt = 0; nt < 16; nt++) {
            const int col = h * 128 + nt * 8 + (tig << 1);
            const int pc = perm64c(col);
            *(half2*)(obuf + (rowbase + m0 + gq) * 1024 + pc) =
                __floats2half2_rn(o[nt][0], o[nt][1]);
            *(half2*)(obuf + (rowbase + m0 + gq + 8) * 1024 + pc) =
                __floats2half2_rn(o[nt][2], o[nt][3]);
        }
    }
}

// ---------------------------------------------------------------------------
// host launcher — 8 launches; attention is #4 (profiled by ncu)
// ---------------------------------------------------------------------------
extern "C" void kernel_launch(void* const* d_in, const int* in_sizes, int n_in,
                              void* d_out, int out_size)
{
    const float* group_x = (const float*)d_in[0];
    const float* context = (const float*)d_in[1];
    const float* W_ada   = (const float*)d_in[2];
    const float* b_ada   = (const float*)d_in[3];
    const float* scale1  = (const float*)d_in[4];
    const float* W_qkv   = (const float*)d_in[5];
    const float* b_qkv   = (const float*)d_in[6];
    const float* W_out   = (const float*)d_in[7];
    const float* b_out   = (const float*)d_in[8];
    const float* scale2  = (const float*)d_in[9];
    const float* W_ff1   = (const float*)d_in[10];
    const float* b_ff1   = (const float*)d_in[11];
    const float* W_ff2   = (const float*)d_in[12];
    const float* b_ff2   = (const float*)d_in[13];
    float* out = (float*)d_out;

    float *ada, *res2;
    __half *x1, *qkv, *obuf, *hbuf, *h1, *wqkv, *wout, *wff1, *wff2;
    float2* rope;
    cudaGetSymbolAddress((void**)&ada,  g_ada);
    cudaGetSymbolAddress((void**)&x1,   g_x1);
    cudaGetSymbolAddress((void**)&qkv,  g_qkv);
    cudaGetSymbolAddress((void**)&obuf, g_o);
    cudaGetSymbolAddress((void**)&res2, g_res);
    cudaGetSymbolAddress((void**)&hbuf, g_h);
    cudaGetSymbolAddress((void**)&h1,   g_h1);
    cudaGetSymbolAddress((void**)&rope, g_rope);
    cudaGetSymbolAddress((void**)&wqkv, g_wqkv);
    cudaGetSymbolAddress((void**)&wout, g_wout);
    cudaGetSymbolAddress((void**)&wff1, g_wff1);
    cudaGetSymbolAddress((void**)&wff2, g_wff2);

    cudaFuncSetAttribute(gemm_fp16<1>, cudaFuncAttributeMaxDynamicSharedMemorySize, GEMM_SMEM);
    cudaFuncSetAttribute(gemm_fp16<2>, cudaFuncAttributeMaxDynamicSharedMemorySize, GEMM_SMEM);
    cudaFuncSetAttribute(gemm_fp16<3>, cudaFuncAttributeMaxDynamicSharedMemorySize, GEMM_SMEM);
    cudaFuncSetAttribute(attn_kernel,  cudaFuncAttributeMaxDynamicSharedMemorySize, ATTN_SMEM_BYTES);

    // 1: ada + rope + W_qkv transpose
    prep_kernel<<<3128, 256>>>(context, W_ada, b_ada, ada, rope, W_qkv, wqkv);

    // 2: norm1 (+ wout/wff1/wff2 transposes in extra blocks)
    norm_mod<<<32768 + 9216, 256>>>(group_x, scale1, ada, 0, 1024, x1,
                                    W_out, wout, W_ff1, wff1, W_ff2, wff2);

    // 3: qkv = x1 @ W_qkv + b_qkv -> fp16 natural   (N=3072, K=1024)
    gemm_fp16<3><<<dim3(12, 256), 256, GEMM_SMEM>>>(x1, wqkv, b_qkv, nullptr, qkv,
                                                    3072, 1024, nullptr, nullptr);

    // 4 (profiled): persistent attention
    attn_kernel<<<AT_GRID, 256, ATTN_SMEM_BYTES>>>(qkv, obuf, rope);

    // 5: res2 = group_x + g_msa * (obuf @ W_out + b_out)   (N=1024, K=1024)
    gemm_fp16<2><<<dim3(4, 256), 256, GEMM_SMEM>>>(obuf, wout, b_out, res2, nullptr,
                                                   1024, 1024, group_x, ada + 2048);

    // 6: norm2
    norm_mod<<<32768, 256>>>(res2, scale2, ada, 3072, 4096, hbuf,
                             nullptr, nullptr, nullptr, nullptr, nullptr, nullptr);

    // 7: h1 = gelu(hbuf @ W_ff1 + b_ff1) -> fp16 perm64  (N=4096, K=1024)
    gemm_fp16<1><<<dim3(16, 256), 256, GEMM_SMEM>>>(hbuf, wff1, b_ff1, nullptr, h1,
                                                    4096, 1024, nullptr, nullptr);
    // 8: out = res2 + g_mlp * (h1 @ W_ff2 + b_ff2)        (N=1024, K=4096)
    gemm_fp16<2><<<dim3(4, 256), 256, GEMM_SMEM>>>(h1, wff2, b_ff2, out, nullptr,
                                                   1024, 4096, res2, ada + 5120);
}

// round 17
// speedup vs baseline: 1.0495x; 1.0221x over previous
#include <cuda_runtime.h>
#include <cuda_fp16.h>
#include <cstdint>

// ---------------------------------------------------------------------------
// B=8, L=4096, D=1024, H=8, DH=128, WIN=128; M = 32768.
// Two-stream half-pipeline overlap: rows [0,16384) on stream 0, rows
// [16384,32768) on a forked stream — all kernels are row-local, so the two
// halves fill each other's tails/ramps (attention hides under GEMMs).
// GEMMs: mma.sync m16n8k16 fp16 fp32-acc, CTA 128x256, BK=128, 2-stage.
// ---------------------------------------------------------------------------

__device__ float  g_ada [8 * 6144];
__device__ __half g_x1  [33554432];
__device__ __half g_qkv [100663296];
__device__ __half g_o   [33554432];
__device__ float  g_res [33554432];
__device__ __half g_h   [33554432];
__device__ __half g_h1  [134217728];
__device__ float2 g_rope[8192];
__device__ __half g_wqkv[3145728];
__device__ __half g_wout[1048576];
__device__ __half g_wff1[4194304];
__device__ __half g_wff2[4194304];

// ---------------------------------------------------------------------------
// helpers
// ---------------------------------------------------------------------------
__device__ __forceinline__ float gelu_fast(float x) {
    const float t = 1.5957691216057308f * (x + 0.044715f * x * x * x);
    return __fdividef(x, 1.f + __expf(-t));
}

__device__ __forceinline__ uint32_t smem_u32(const void* p) {
    uint32_t a;
    asm("{ .reg .u64 t; cvta.to.shared.u64 t, %1; cvt.u32.u64 %0, t; }" : "=r"(a) : "l"(p));
    return a;
}

__device__ __forceinline__ uint32_t h2u(half2 h) {
    uint32_t u;
    memcpy(&u, &h, 4);
    return u;
}

__device__ __forceinline__ int perm64h(int k) {
    const int base  = k & ~63;
    const int sb    = (k >> 5) & 1;
    const int b16   = (k >> 4) & 1;
    const int j     = (k & 15) >> 1;
    const int owner = j & 3, hi = j >> 2;
    return base + (owner * 2 + sb) * 8 + b16 * 4 + hi * 2 + (k & 1);
}
__device__ __forceinline__ int perm64c(int col) { return perm64h(col); }

__device__ __forceinline__ void mma16(float* d, uint32_t a0, uint32_t a1,
                                      uint32_t a2, uint32_t a3,
                                      uint32_t b0, uint32_t b1) {
    asm volatile(
        "mma.sync.aligned.m16n8k16.row.col.f32.f16.f16.f32 "
        "{%0,%1,%2,%3}, {%4,%5,%6,%7}, {%8,%9}, {%0,%1,%2,%3};"
        : "+f"(d[0]), "+f"(d[1]), "+f"(d[2]), "+f"(d[3])
        : "r"(a0), "r"(a1), "r"(a2), "r"(a3), "r"(b0), "r"(b1));
}

__device__ __forceinline__ void ldsm_x4(uint32_t& r0, uint32_t& r1,
                                        uint32_t& r2, uint32_t& r3, uint32_t a) {
    asm volatile("ldmatrix.sync.aligned.m8n8.x4.shared.b16 {%0,%1,%2,%3}, [%4];"
                 : "=r"(r0), "=r"(r1), "=r"(r2), "=r"(r3) : "r"(a));
}
__device__ __forceinline__ void ldsm_x4t(uint32_t& r0, uint32_t& r1,
                                         uint32_t& r2, uint32_t& r3, uint32_t a) {
    asm volatile("ldmatrix.sync.aligned.m8n8.x4.trans.shared.b16 {%0,%1,%2,%3}, [%4];"
                 : "=r"(r0), "=r"(r1), "=r"(r2), "=r"(r3) : "r"(a));
}

__device__ __forceinline__ uint4 lds128(uint32_t a) {
    uint4 v;
    asm volatile("ld.shared.v4.u32 {%0,%1,%2,%3}, [%4];"
                 : "=r"(v.x), "=r"(v.y), "=r"(v.z), "=r"(v.w) : "r"(a));
    return v;
}

__device__ __forceinline__ void cp16(uint32_t dst, const void* src) {
    asm volatile("cp.async.cg.shared.global [%0], [%1], 16;" :: "r"(dst), "l"(src));
}
#define CP_COMMIT() asm volatile("cp.async.commit_group;" ::: "memory")
#define CP_WAIT1()  asm volatile("cp.async.wait_group 1;"  ::: "memory")
#define CP_WAIT0()  asm volatile("cp.async.wait_group 0;"  ::: "memory")

// ---------------------------------------------------------------------------
// device transpose helper: Wt[n][perm64(k)] = fp16(W[k][n]), 32x32 tile
// ---------------------------------------------------------------------------
__device__ __forceinline__ void dev_transpose(
    const float* __restrict__ W, __half* __restrict__ Wt,
    int K, int N, int kb, int nb, float* sh)
{
    const int tx = threadIdx.x & 31, ty = threadIdx.x >> 5;
    #pragma unroll
    for (int i = 0; i < 4; i++)
        sh[(ty + 8 * i) * 33 + tx] = W[(size_t)(kb + ty + 8 * i) * N + nb + tx];
    __syncthreads();
    #pragma unroll
    for (int i = 0; i < 4; i++)
        Wt[(size_t)(nb + ty + 8 * i) * K + perm64h(kb + tx)] =
            __float2half_rn(sh[tx * 33 + ty + 8 * i]);
}

// ---------------------------------------------------------------------------
// Kernel 1: prep = ada + rope + ALL weight transposes (pre-fork, stream 0)
//   blocks: [0,24) ada | [24,56) rope | [56,3128) wqkv | [3128,4152) wout |
//           [4152,8248) wff1 | [8248,12344) wff2
// ---------------------------------------------------------------------------
__global__ void __launch_bounds__(256) prep_kernel(
    const float* __restrict__ ctx, const float* __restrict__ W_ada,
    const float* __restrict__ b_ada, float* __restrict__ ada,
    float2* __restrict__ rope,
    const float* __restrict__ W_qkv, __half* __restrict__ wqkv,
    const float* __restrict__ W_out, __half* __restrict__ wout,
    const float* __restrict__ W_ff1, __half* __restrict__ wff1,
    const float* __restrict__ W_ff2, __half* __restrict__ wff2)
{
    __shared__ float sh[8448];
    const int b = blockIdx.x;
    if (b < 24) {
        for (int i = threadIdx.x; i < 8192; i += 256) {
            float c = ctx[i];
            sh[i] = c / (1.f + __expf(-c));
        }
        __syncthreads();
        const int col = b * 256 + threadIdx.x;
        float acc[8] = {0, 0, 0, 0, 0, 0, 0, 0};
        for (int k = 0; k < 1024; k++) {
            float w = W_ada[(size_t)k * 6144 + col];
            #pragma unroll
            for (int bb = 0; bb < 8; bb++) acc[bb] += sh[bb * 1024 + k] * w;
        }
        float bv = b_ada[col];
        #pragma unroll
        for (int bb = 0; bb < 8; bb++) ada[bb * 6144 + col] = acc[bb] + bv;
    } else if (b < 56) {
        int idx = (b - 24) * 256 + threadIdx.x;
        if (idx < 8192) {
            int pos = idx >> 6;
            int i   = idx & 63;
            float freq = powf(10000.f, -(float)(2 * i) / 128.f);
            float ang  = (float)pos * freq;
            rope[idx] = make_float2(sinf(ang), cosf(ang));
        }
    } else if (b < 3128) {
        const int t = b - 56;
        dev_transpose(W_qkv, wqkv, 1024, 3072, (t / 96) * 32, (t % 96) * 32, sh);
    } else if (b < 4152) {
        const int t = b - 3128;
        dev_transpose(W_out, wout, 1024, 1024, (t / 32) * 32, (t % 32) * 32, sh);
    } else if (b < 8248) {
        const int t = b - 4152;
        dev_transpose(W_ff1, wff1, 1024, 4096, (t / 128) * 32, (t % 128) * 32, sh);
    } else {
        const int t = b - 8248;
        dev_transpose(W_ff2, wff2, 4096, 1024, (t / 32) * 32, (t % 32) * 32, sh);
    }
}

// ---------------------------------------------------------------------------
// Kernel 2: rmsnorm + modulate -> fp16 perm64 (row-offset for half-pipelines)
// ---------------------------------------------------------------------------
__global__ void __launch_bounds__(256) norm_mod(
    const float* __restrict__ x, const float* __restrict__ scale,
    const float* __restrict__ ada, int shOff, int scOff,
    __half* __restrict__ y, int rowOff)
{
    __shared__ float sh[8];
    const int row = rowOff + blockIdx.x;
    const int b = row >> 12;
    const float4 v = ((const float4*)(x + (size_t)row * 1024))[threadIdx.x];

    float ss = v.x * v.x + v.y * v.y + v.z * v.z + v.w * v.w;
    #pragma unroll
    for (int o = 16; o > 0; o >>= 1) ss += __shfl_xor_sync(0xffffffffu, ss, o);
    if ((threadIdx.x & 31) == 0) sh[threadIdx.x >> 5] = ss;
    __syncthreads();
    float tot = 0.f;
    #pragma unroll
    for (int i = 0; i < 8; i++) tot += sh[i];
    const float r = rsqrtf(tot * (1.f / 1024.f) + 1e-5f);

    const int c = threadIdx.x * 4;
    const float* ab = ada + b * 6144;
    const float4 s   = *(const float4*)(scale + c);
    const float4 shv = *(const float4*)(ab + shOff + c);
    const float4 scm = *(const float4*)(ab + scOff + c);
    float o0 = v.x * r * s.x * (1.f + scm.x) + shv.x;
    float o1 = v.y * r * s.y * (1.f + scm.y) + shv.y;
    float o2 = v.z * r * s.z * (1.f + scm.z) + shv.z;
    float o3 = v.w * r * s.w * (1.f + scm.w) + shv.w;
    __half* yr = y + (size_t)row * 1024;
    *(half2*)(yr + perm64c(c))     = __floats2half2_rn(o0, o1);
    *(half2*)(yr + perm64c(c + 2)) = __floats2half2_rn(o2, o3);
}

// ---------------------------------------------------------------------------
// Kernel 4: fp16 GEMM, CTA 128x256, BK=128, 2-stage (196KB smem), mOff.
// ---------------------------------------------------------------------------
#define STAGE_BYTES 98304
#define GEMM_SMEM  (2 * STAGE_BYTES)

template <int MODE>
__global__ void __launch_bounds__(256, 1) gemm_fp16(
    const __half* __restrict__ A, const __half* __restrict__ Bt,
    const float* __restrict__ bias,
    float* __restrict__ C, __half* __restrict__ Ch,
    int N, int K,
    const float* __restrict__ res, const float* __restrict__ gate,
    int mOff)
{
    extern __shared__ char smem[];
    const uint32_t sm_u = smem_u32(smem);

    const int tid  = threadIdx.x;
    const int lane = tid & 31;
    const int warp = tid >> 5;
    const int g    = lane >> 2, tig = lane & 3;
    const int wm   = warp & 1;
    const int wn   = warp >> 1;
    const int cm   = mOff + (blockIdx.y << 7);
    const int cn   = blockIdx.x << 8;
    const int KT   = K >> 7;

    const int f_row = tid >> 4;
    const int f_pos = tid & 15;

    auto fill = [&](int kt, int s) {
        const uint32_t sb_ = sm_u + s * STAGE_BYTES;
        const __half* Ag = A + (size_t)(cm + f_row) * K + (kt << 7) + f_pos * 8;
        #pragma unroll
        for (int i = 0; i < 8; i++) {
            const int row = f_row + i * 16;
            cp16(sb_ + row * 256 + (((f_pos & 7) ^ (row & 7)) << 4) + ((f_pos & 8) << 4),
                 Ag + (size_t)i * 16 * K);
        }
        const __half* Bg = Bt + (size_t)(cn + f_row) * K + (kt << 7) + f_pos * 8;
        #pragma unroll
        for (int i = 0; i < 16; i++) {
            const int row = f_row + i * 16;
            cp16(sb_ + 32768 + row * 256 + (((f_pos & 7) ^ (row & 7)) << 4) + ((f_pos & 8) << 4),
                 Bg + (size_t)i * 16 * K);
        }
    };

    float acc[4][8][4];
    #pragma unroll
    for (int mt = 0; mt < 4; mt++)
        #pragma unroll
        for (int nt = 0; nt < 8; nt++)
            #pragma unroll
            for (int i = 0; i < 4; i++) acc[mt][nt][i] = 0.f;

    fill(0, 0); CP_COMMIT();

    for (int kt = 0; kt < KT; kt++) {
        const int buf = kt & 1;
        if (kt + 1 < KT) { fill(kt + 1, buf ^ 1); CP_COMMIT(); CP_WAIT1(); }
        else             { CP_WAIT0(); }
        __syncthreads();

        const uint32_t a_base = sm_u + buf * STAGE_BYTES;
        const uint32_t b_base = a_base + 32768;
        #pragma unroll
        for (int sb = 0; sb < 4; sb++) {
            const int half64 = sb >> 1;
            const int chn    = (tig << 1) | (sb & 1);
            const int coff   = half64 << 7;
            uint4 al[4], ah[4];
            #pragma unroll
            for (int mt = 0; mt < 4; mt++) {
                const int rl = wm * 64 + mt * 16 + g;
                al[mt] = lds128(a_base + rl * 256 + coff + ((chn ^ (rl & 7)) << 4));
                ah[mt] = lds128(a_base + (rl + 8) * 256 + coff + ((chn ^ (rl & 7)) << 4));
            }
            #pragma unroll
            for (int nt = 0; nt < 8; nt++) {
                const int rb = wn * 64 + nt * 8 + g;
                const uint4 bb = lds128(b_base + rb * 256 + coff + ((chn ^ (rb & 7)) << 4));
                #pragma unroll
                for (int mt = 0; mt < 4; mt++) {
                    mma16(acc[mt][nt], al[mt].x, ah[mt].x, al[mt].y, ah[mt].y,
                          bb.x, bb.y);
                    mma16(acc[mt][nt], al[mt].z, ah[mt].z, al[mt].w, ah[mt].w,
                          bb.z, bb.w);
                }
            }
        }
        __syncthreads();
    }

    const int bb_i = cm >> 12;
    #pragma unroll
    for (int mt = 0; mt < 4; mt++) {
        const int row0 = cm + wm * 64 + mt * 16 + g;
        #pragma unroll
        for (int nt = 0; nt < 8; nt++) {
            const int col = cn + wn * 64 + nt * 8 + (tig << 1);
            const float bi0 = bias[col], bi1 = bias[col + 1];
            float v0 = acc[mt][nt][0] + bi0;
            float v1 = acc[mt][nt][1] + bi1;
            float v2 = acc[mt][nt][2] + bi0;
            float v3 = acc[mt][nt][3] + bi1;
            if (MODE == 1) {
                v0 = gelu_fast(v0); v1 = gelu_fast(v1);
                v2 = gelu_fast(v2); v3 = gelu_fast(v3);
                const int p = perm64c(col);
                *(half2*)(Ch + (size_t)row0 * N + p)       = __floats2half2_rn(v0, v1);
                *(half2*)(Ch + (size_t)(row0 + 8) * N + p) = __floats2half2_rn(v2, v3);
            } else if (MODE == 3) {
                *(half2*)(Ch + (size_t)row0 * N + col)       = __floats2half2_rn(v0, v1);
                *(half2*)(Ch + (size_t)(row0 + 8) * N + col) = __floats2half2_rn(v2, v3);
            } else {
                if (MODE == 2) {
                    const float g0 = gate[bb_i * 6144 + col];
                    const float g1 = gate[bb_i * 6144 + col + 1];
                    const float2 r0 = *(const float2*)(res + (size_t)row0 * N + col);
                    const float2 r1 = *(const float2*)(res + (size_t)(row0 + 8) * N + col);
                    v0 = r0.x + g0 * v0;  v1 = r0.y + g1 * v1;
                    v2 = r1.x + g0 * v2;  v3 = r1.y + g1 * v3;
                }
                *(float2*)(C + (size_t)row0 * N + col)       = make_float2(v0, v1);
                *(float2*)(C + (size_t)(row0 + 8) * N + col) = make_float2(v2, v3);
            }
        }
    }
}

// ---------------------------------------------------------------------------
// Kernel 5: persistent windowed attention over a tile range [tileOff, tileEnd)
// ---------------------------------------------------------------------------
#define AT_BUF  98304
#define ATTN_SMEM_BYTES AT_BUF
#define AT_GRID 296

__global__ void __launch_bounds__(256, 2) attn_kernel(
    const __half* __restrict__ qkv, __half* __restrict__ obuf,
    const float2* __restrict__ rope, int tileOff, int tileEnd)
{
    extern __shared__ char sha[];
    const uint32_t sm_u = smem_u32(sha);

    const int tid  = threadIdx.x;
    const int lane = tid & 31, warp = tid >> 5;
    const int tig  = lane & 3;

    const int s_row = tid >> 4, s_ch = tid & 15;

    auto stage = [&](int tile) {
        const int w = tile >> 3, h = tile & 7;
        const size_t rb = (size_t)w * 128;
        const __half* base = qkv + (rb + s_row) * 3072 + h * 128 + s_ch * 8;
        #pragma unroll
        for (int i = 0; i < 8; i++) {
            const int r = s_row + i * 16;
            const uint32_t off = r * 256 + ((s_ch ^ (r & 7)) << 4);
            const __half* src = base + (size_t)i * 16 * 3072;
            cp16(sm_u + off,         src);
            cp16(sm_u + 32768 + off, src + 1024);
            cp16(sm_u + 65536 + off, src + 2048);
        }
    };

    const int m0 = warp * 16;
    const int l7 = lane & 7;
    const int a_row = m0 + l7 + ((lane & 8) ? 8 : 0);
    const int a_kc8 = (lane & 16) ? 1 : 0;
    const int b_row = l7 + ((lane & 16) ? 8 : 0);
    const int b_kc8 = (lane & 8) ? 1 : 0;
    const int v_row = l7 + ((lane & 8) ? 8 : 0);
    const int v_dc8 = (lane & 16) ? 1 : 0;

    const uint32_t q_u = sm_u;
    const uint32_t k_u = sm_u + 32768;
    const uint32_t v_u = sm_u + 65536;

    if (tileOff + blockIdx.x < tileEnd) stage(tileOff + blockIdx.x);
    CP_COMMIT();

    for (int tile = tileOff + blockIdx.x; tile < tileEnd; tile += AT_GRID) {
        CP_WAIT0();
        __syncthreads();

        const int h = tile & 7;
        const size_t rowbase = (size_t)(tile >> 3) * 128;

        #pragma unroll
        for (int it = 0; it < 16; it++) {
            const int task = tid + it * 256;
            const int i  = task >> 5;
            const int dp = task & 31;
            const int d  = dp << 1;
            const int clo = (d >> 3) ^ (i & 7);
            const int chi = ((d + 64) >> 3) ^ (i & 7);
            const int ib  = (d << 1) & 15;
            const uint32_t lo = i * 256 + (clo << 4) + ib;
            const uint32_t hi = i * 256 + (chi << 4) + ib;
            const float2 sc_lo = rope[i * 64 + dp];
            const float2 sc_hi = rope[i * 64 + dp + 32];
            {
                half2* plo = (half2*)(sha + lo);
                half2* phi = (half2*)(sha + hi);
                float2 a = __half22float2(*plo);
                float2 b = __half22float2(*phi);
                *plo = __floats2half2_rn(a.x * sc_lo.y - b.x * sc_lo.x,
                                         a.y * sc_lo.y - b.y * sc_lo.x);
                *phi = __floats2half2_rn(b.x * sc_hi.y + a.x * sc_hi.x,
                                         b.y * sc_hi.y + a.y * sc_hi.x);
            }
            {
                half2* plo = (half2*)(sha + 32768 + lo);
                half2* phi = (half2*)(sha + 32768 + hi);
                float2 a = __half22float2(*plo);
                float2 b = __half22float2(*phi);
                *plo = __floats2half2_rn(a.x * sc_lo.y - b.x * sc_lo.x,
                                         a.y * sc_lo.y - b.y * sc_lo.x);
                *phi = __floats2half2_rn(b.x * sc_hi.y + a.x * sc_hi.x,
                                         b.y * sc_hi.y + a.y * sc_hi.x);
            }
        }
        __syncthreads();

        float acc[16][4];
        #pragma unroll
        for (int nt = 0; nt < 16; nt++)
            #pragma unroll
            for (int i = 0; i < 4; i++) acc[nt][i] = 0.f;

        #pragma unroll
        for (int kc = 0; kc < 8; kc++) {
            uint32_t a0, a1, a2, a3;
            const int ca = (kc * 2 + a_kc8) ^ (a_row & 7);
            ldsm_x4(a0, a1, a2, a3, q_u + a_row * 256 + (ca << 4));
            #pragma unroll
            for (int np = 0; np < 8; np++) {
                const int row = np * 16 + b_row;
                const int cb = (kc * 2 + b_kc8) ^ (row & 7);
                uint32_t b0, b1, c0, c1;
                ldsm_x4(b0, b1, c0, c1, k_u + row * 256 + (cb << 4));
                mma16(acc[2 * np],     a0, a1, a2, a3, b0, b1);
                mma16(acc[2 * np + 1], a0, a1, a2, a3, c0, c1);
            }
        }

        const float scl = 0.08838834764831845f;
        float mx0 = -1e30f, mx1 = -1e30f;
        #pragma unroll
        for (int nt = 0; nt < 16; nt++) {
            acc[nt][0] *= scl; acc[nt][1] *= scl;
            acc[nt][2] *= scl; acc[nt][3] *= scl;
            mx0 = fmaxf(mx0, fmaxf(acc[nt][0], acc[nt][1]));
            mx1 = fmaxf(mx1, fmaxf(acc[nt][2], acc[nt][3]));
        }
        mx0 = fmaxf(mx0, __shfl_xor_sync(0xffffffffu, mx0, 1));
        mx0 = fmaxf(mx0, __shfl_xor_sync(0xffffffffu, mx0, 2));
        mx1 = fmaxf(mx1, __shfl_xor_sync(0xffffffffu, mx1, 1));
        mx1 = fmaxf(mx1, __shfl_xor_sync(0xffffffffu, mx1, 2));

        float s0 = 0.f, s1 = 0.f;
        #pragma unroll
        for (int nt = 0; nt < 16; nt++) {
            acc[nt][0] = __expf(acc[nt][0] - mx0);
            acc[nt][1] = __expf(acc[nt][1] - mx0);
            acc[nt][2] = __expf(acc[nt][2] - mx1);
            acc[nt][3] = __expf(acc[nt][3] - mx1);
            s0 += acc[nt][0] + acc[nt][1];
            s1 += acc[nt][2] + acc[nt][3];
        }
        s0 += __shfl_xor_sync(0xffffffffu, s0, 1);
        s0 += __shfl_xor_sync(0xffffffffu, s0, 2);
        s1 += __shfl_xor_sync(0xffffffffu, s1, 1);
        s1 += __shfl_xor_sync(0xffffffffu, s1, 2);
        const float i0 = 1.f / s0, i1 = 1.f / s1;

        uint32_t p[32];
        #pragma unroll
        for (int kc = 0; kc < 8; kc++) {
            p[4 * kc + 0] = h2u(__floats2half2_rn(acc[2 * kc][0] * i0, acc[2 * kc][1] * i0));
            p[4 * kc + 1] = h2u(__floats2half2_rn(acc[2 * kc][2] * i1, acc[2 * kc][3] * i1));
            p[4 * kc + 2] = h2u(__floats2half2_rn(acc[2 * kc + 1][0] * i0, acc[2 * kc + 1][1] * i0));
            p[4 * kc + 3] = h2u(__floats2half2_rn(acc[2 * kc + 1][2] * i1, acc[2 * kc + 1][3] * i1));
        }

        float o[16][4];
        #pragma unroll
        for (int nt = 0; nt < 16; nt++)
            #pragma unroll
            for (int i = 0; i < 4; i++) o[nt][i] = 0.f;

        #pragma unroll
        for (int kc = 0; kc < 8; kc++) {
            #pragma unroll
            for (int dp = 0; dp < 8; dp++) {
                const int row = kc * 16 + v_row;
                const int cv = (dp * 2 + v_dc8) ^ (row & 7);
                uint32_t b0, b1, c0, c1;
                ldsm_x4t(b0, b1, c0, c1, v_u + row * 256 + (cv << 4));
                mma16(o[2 * dp],     p[4 * kc], p[4 * kc + 1], p[4 * kc + 2], p[4 * kc + 3], b0, b1);
                mma16(o[2 * dp + 1], p[4 * kc], p[4 * kc + 1], p[4 * kc + 2], p[4 * kc + 3], c0, c1);
            }
        }

        __syncthreads();
        if (tile + AT_GRID < tileEnd) stage(tile + AT_GRID);
        CP_COMMIT();

        const int gq = lane >> 2;
        #pragma unroll
        for (int nt = 0; nt < 16; nt++) {
            const int col = h * 128 + nt * 8 + (tig << 1);
            const int pc = perm64c(col);
            *(half2*)(obuf + (rowbase + m0 + gq) * 1024 + pc) =
                __floats2half2_rn(o[nt][0], o[nt][1]);
            *(half2*)(obuf + (rowbase + m0 + gq + 8) * 1024 + pc) =
                __floats2half2_rn(o[nt][2], o[nt][3]);
        }
    }
}

// ---------------------------------------------------------------------------
// host launcher — prep on stream 0, then two half-pipelines on 2 streams.
// ---------------------------------------------------------------------------
extern "C" void kernel_launch(void* const* d_in, const int* in_sizes, int n_in,
                              void* d_out, int out_size)
{
    const float* group_x = (const float*)d_in[0];
    const float* context = (const float*)d_in[1];
    const float* W_ada   = (const float*)d_in[2];
    const float* b_ada   = (const float*)d_in[3];
    const float* scale1  = (const float*)d_in[4];
    const float* W_qkv   = (const float*)d_in[5];
    const float* b_qkv   = (const float*)d_in[6];
    const float* W_out   = (const float*)d_in[7];
    const float* b_out   = (const float*)d_in[8];
    const float* scale2  = (const float*)d_in[9];
    const float* W_ff1   = (const float*)d_in[10];
    const float* b_ff1   = (const float*)d_in[11];
    const float* W_ff2   = (const float*)d_in[12];
    const float* b_ff2   = (const float*)d_in[13];
    float* out = (float*)d_out;

    float *ada, *res2;
    __half *x1, *qkv, *obuf, *hbuf, *h1, *wqkv, *wout, *wff1, *wff2;
    float2* rope;
    cudaGetSymbolAddress((void**)&ada,  g_ada);
    cudaGetSymbolAddress((void**)&x1,   g_x1);
    cudaGetSymbolAddress((void**)&qkv,  g_qkv);
    cudaGetSymbolAddress((void**)&obuf, g_o);
    cudaGetSymbolAddress((void**)&res2, g_res);
    cudaGetSymbolAddress((void**)&hbuf, g_h);
    cudaGetSymbolAddress((void**)&h1,   g_h1);
    cudaGetSymbolAddress((void**)&rope, g_rope);
    cudaGetSymbolAddress((void**)&wqkv, g_wqkv);
    cudaGetSymbolAddress((void**)&wout, g_wout);
    cudaGetSymbolAddress((void**)&wff1, g_wff1);
    cudaGetSymbolAddress((void**)&wff2, g_wff2);

    cudaFuncSetAttribute(gemm_fp16<1>, cudaFuncAttributeMaxDynamicSharedMemorySize, GEMM_SMEM);
    cudaFuncSetAttribute(gemm_fp16<2>, cudaFuncAttributeMaxDynamicSharedMemorySize, GEMM_SMEM);
    cudaFuncSetAttribute(gemm_fp16<3>, cudaFuncAttributeMaxDynamicSharedMemorySize, GEMM_SMEM);
    cudaFuncSetAttribute(attn_kernel,  cudaFuncAttributeMaxDynamicSharedMemorySize, ATTN_SMEM_BYTES);

    // fork stream + events (created per call; host-side objects)
    cudaStream_t s2;
    cudaStreamCreateWithFlags(&s2, cudaStreamNonBlocking);
    cudaEvent_t evFork, evJoin;
    cudaEventCreateWithFlags(&evFork, cudaEventDisableTiming);
    cudaEventCreateWithFlags(&evJoin, cudaEventDisableTiming);

    // prep on stream 0
    prep_kernel<<<12344, 256>>>(context, W_ada, b_ada, ada, rope,
                                W_qkv, wqkv, W_out, wout, W_ff1, wff1, W_ff2, wff2);
    cudaEventRecord(evFork, 0);
    cudaStreamWaitEvent(s2, evFork, 0);

    // two half-pipelines (rows [0,16384) on stream 0, [16384,32768) on s2)
    for (int hf = 0; hf < 2; hf++) {
        cudaStream_t st = hf ? s2 : (cudaStream_t)0;
        const int mOff = hf * 16384;
        const int tOff = hf * 1024;

        norm_mod<<<16384, 256, 0, st>>>(group_x, scale1, ada, 0, 1024, x1, mOff);

        gemm_fp16<3><<<dim3(12, 128), 256, GEMM_SMEM, st>>>(
            x1, wqkv, b_qkv, nullptr, qkv, 3072, 1024, nullptr, nullptr, mOff);

        attn_kernel<<<AT_GRID, 256, ATTN_SMEM_BYTES, st>>>(
            qkv, obuf, rope, tOff, tOff + 1024);

        gemm_fp16<2><<<dim3(4, 128), 256, GEMM_SMEM, st>>>(
            obuf, wout, b_out, res2, nullptr, 1024, 1024, group_x, ada + 2048, mOff);

        norm_mod<<<16384, 256, 0, st>>>(res2, scale2, ada, 3072, 4096, hbuf, mOff);

        gemm_fp16<1><<<dim3(16, 128), 256, GEMM_SMEM, st>>>(
            hbuf, wff1, b_ff1, nullptr, h1, 4096, 1024, nullptr, nullptr, mOff);

        gemm_fp16<2><<<dim3(4, 128), 256, GEMM_SMEM, st>>>(
            h1, wff2, b_ff2, out, nullptr, 1024, 4096, res2, ada + 5120, mOff);
    }

    // join s2 back into stream 0 (required for capture completeness)
    cudaEventRecord(evJoin, s2);
    cudaStreamWaitEvent(0, evJoin, 0);
}